// round 2
// baseline (speedup 1.0000x reference)
#include <cuda_runtime.h>
#include <cstdint>

#define NN 20000
#define NE 640000
#define HC 256      // H * C = 4 * 64
#define NH 4
#define NC 64

// ---------------- scratch (static device globals; no allocation) ----------
__device__ float g_xh[NN * HC];        // per-layer transformed node features
__device__ float g_agg[NN * HC];       // aggregation accumulator / h between layers
__device__ float g_asrc[NN * NH];
__device__ float g_adst[NN * NH];
__device__ float g_amax[NN * NH];      // float bits, atomic max via int punning
__device__ float g_denom[NN * NH];
__device__ float g_alpha[NE * NH];     // raw alpha, then exp(alpha - max)
__device__ float g_ce[2 * NH];         // per-head edge-attr coefficient, both layers

// ---------------- helpers -------------------------------------------------
__device__ __forceinline__ void atomicMaxF(float* addr, float v) {
    if (v >= 0.f) atomicMax((int*)addr, __float_as_int(v));
    else          atomicMin((unsigned int*)addr, __float_as_uint(v));
}

__device__ __forceinline__ void red_add_v4(float* addr, float a, float b, float c, float d) {
    asm volatile("red.global.add.v4.f32 [%0], {%1,%2,%3,%4};"
                 :: "l"(addr), "f"(a), "f"(b), "f"(c), "f"(d) : "memory");
}

// ---------------- tiny setup kernels --------------------------------------
// ce[h] = sum_c W_e[h*64+c] * a_e[h*64+c]  (because edge_attr is [E,1])
__global__ void k_ce(const float* __restrict__ We1, const float* __restrict__ ae1,
                     const float* __restrict__ We2, const float* __restrict__ ae2) {
    __shared__ float s1[256], s2[256];
    int t = threadIdx.x;
    s1[t] = We1[t] * ae1[t];
    s2[t] = We2[t] * ae2[t];
    __syncthreads();
    if (t < 8) {
        const float* s = (t >= 4) ? s2 : s1;
        int h = t & 3;
        float sum = 0.f;
#pragma unroll
        for (int c = 0; c < 64; c++) sum += s[h * 64 + c];
        g_ce[t] = sum;
    }
}

__global__ void k_init_nodes() {
    int i = blockIdx.x * blockDim.x + threadIdx.x;
    if (i < NN * NH) {
        g_denom[i] = 0.f;
        ((unsigned*)g_amax)[i] = 0xFF800000u;  // -inf
    }
}

__global__ void k_zero_agg() {  // exactly NN*HC/4 threads
    int i = blockIdx.x * blockDim.x + threadIdx.x;
    ((float4*)g_agg)[i] = make_float4(0.f, 0.f, 0.f, 0.f);
}

// ---------------- GEMM: xh = X @ W, fused alpha_src/alpha_dst -------------
// grid: (ceil(NN/64), 4 heads), block 256. Tile 64x64, BK=32, 4x4 per thread.
// X==nullptr means read from g_agg (layer 2 input).
__global__ void k_gemm(const float* __restrict__ X, const float* __restrict__ W,
                       const float* __restrict__ a_src, const float* __restrict__ a_dst,
                       int K) {
    __shared__ float As[32][68];   // transposed: As[k][m]
    __shared__ float Bs[32][68];   // Bs[k][n]
    const float* Xp = X ? X : g_agg;

    int tid = threadIdx.x;
    int r0 = blockIdx.x * 64;
    int head = blockIdx.y;
    int c0 = head * 64;
    int tx = tid & 15, ty = tid >> 4;
    int m0 = ty * 4, n0 = tx * 4;

    float acc[4][4] = {};

    for (int kk = 0; kk < K; kk += 32) {
#pragma unroll
        for (int j = 0; j < 2; j++) {
            int i = tid + 256 * j;
            int row = i >> 3;
            int kq = i & 7;
            float4 v = make_float4(0.f, 0.f, 0.f, 0.f);
            int gr = r0 + row;
            if (gr < NN) v = *(const float4*)&Xp[(size_t)gr * K + kk + kq * 4];
            As[kq * 4 + 0][row] = v.x;
            As[kq * 4 + 1][row] = v.y;
            As[kq * 4 + 2][row] = v.z;
            As[kq * 4 + 3][row] = v.w;
        }
#pragma unroll
        for (int j = 0; j < 2; j++) {
            int i = tid + 256 * j;
            int kr = i >> 4;
            int cq = i & 15;
            float4 v = *(const float4*)&W[(size_t)(kk + kr) * HC + c0 + cq * 4];
            *(float4*)&Bs[kr][cq * 4] = v;
        }
        __syncthreads();
#pragma unroll
        for (int k = 0; k < 32; k++) {
            float4 av = *(float4*)&As[k][m0];
            float4 bv = *(float4*)&Bs[k][n0];
            float ar[4] = {av.x, av.y, av.z, av.w};
            float br[4] = {bv.x, bv.y, bv.z, bv.w};
#pragma unroll
            for (int i = 0; i < 4; i++)
#pragma unroll
                for (int j = 0; j < 4; j++)
                    acc[i][j] = fmaf(ar[i], br[j], acc[i][j]);
        }
        __syncthreads();
    }

    float4 as4 = *(const float4*)&a_src[head * 64 + n0];
    float4 ad4 = *(const float4*)&a_dst[head * 64 + n0];

#pragma unroll
    for (int i = 0; i < 4; i++) {
        int gr = r0 + m0 + i;
        float ps = acc[i][0] * as4.x + acc[i][1] * as4.y + acc[i][2] * as4.z + acc[i][3] * as4.w;
        float pd = acc[i][0] * ad4.x + acc[i][1] * ad4.y + acc[i][2] * ad4.z + acc[i][3] * ad4.w;
#pragma unroll
        for (int o = 8; o; o >>= 1) {
            ps += __shfl_down_sync(0xffffffffu, ps, o, 16);
            pd += __shfl_down_sync(0xffffffffu, pd, o, 16);
        }
        if (gr < NN) {
            *(float4*)&g_xh[(size_t)gr * HC + c0 + n0] =
                make_float4(acc[i][0], acc[i][1], acc[i][2], acc[i][3]);
            if (tx == 0) {
                g_asrc[gr * NH + head] = ps;
                g_adst[gr * NH + head] = pd;
            }
        }
    }
}

// ---------------- edge kernels --------------------------------------------
__global__ void k_edge_alpha(const int* __restrict__ src, const int* __restrict__ dst,
                             const float* __restrict__ eattr, int ce_off) {
    int e = blockIdx.x * blockDim.x + threadIdx.x;
    if (e >= NE) return;
    int s = src[e], d = dst[e];
    float4 as = *(const float4*)&g_asrc[s * 4];
    float4 ad = *(const float4*)&g_adst[d * 4];
    float ea = eattr[e];
    float a0 = as.x + ad.x + ea * g_ce[ce_off + 0];
    float a1 = as.y + ad.y + ea * g_ce[ce_off + 1];
    float a2 = as.z + ad.z + ea * g_ce[ce_off + 2];
    float a3 = as.w + ad.w + ea * g_ce[ce_off + 3];
    a0 = a0 >= 0.f ? a0 : 0.2f * a0;
    a1 = a1 >= 0.f ? a1 : 0.2f * a1;
    a2 = a2 >= 0.f ? a2 : 0.2f * a2;
    a3 = a3 >= 0.f ? a3 : 0.2f * a3;
    *(float4*)&g_alpha[(size_t)e * 4] = make_float4(a0, a1, a2, a3);
    atomicMaxF(&g_amax[d * 4 + 0], a0);
    atomicMaxF(&g_amax[d * 4 + 1], a1);
    atomicMaxF(&g_amax[d * 4 + 2], a2);
    atomicMaxF(&g_amax[d * 4 + 3], a3);
}

__global__ void k_edge_expsum(const int* __restrict__ dst) {
    int e = blockIdx.x * blockDim.x + threadIdx.x;
    if (e >= NE) return;
    int d = dst[e];
    float4 al = *(const float4*)&g_alpha[(size_t)e * 4];
    float4 mx = *(const float4*)&g_amax[d * 4];
    float p0 = __expf(al.x - mx.x);
    float p1 = __expf(al.y - mx.y);
    float p2 = __expf(al.z - mx.z);
    float p3 = __expf(al.w - mx.w);
    *(float4*)&g_alpha[(size_t)e * 4] = make_float4(p0, p1, p2, p3);
    red_add_v4(&g_denom[d * 4], p0, p1, p2, p3);
}

// warp per edge: w = p/denom (written to wout), msg = xh[src]*w*atten -> agg[dst]
__global__ void k_edge_agg(const int* __restrict__ src, const int* __restrict__ dst,
                           const float* __restrict__ atten, float* __restrict__ wout) {
    int gw = (blockIdx.x * blockDim.x + threadIdx.x) >> 5;
    int lane = threadIdx.x & 31;
    if (gw >= NE) return;
    int e = gw;
    int s = src[e], d = dst[e];
    float4 p = *(const float4*)&g_alpha[(size_t)e * 4];
    float4 dn = *(const float4*)&g_denom[d * 4];
    float w0 = p.x / (dn.x + 1e-16f);
    float w1 = p.y / (dn.y + 1e-16f);
    float w2 = p.z / (dn.z + 1e-16f);
    float w3 = p.w / (dn.w + 1e-16f);
    if (lane == 0) *(float4*)&wout[(size_t)e * 4] = make_float4(w0, w1, w2, w3);
    float at = atten[e];
    int h = lane >> 3;
    float coef = (h == 0 ? w0 : h == 1 ? w1 : h == 2 ? w2 : w3) * at;
    int c0 = lane * 8;
    const float* xs = &g_xh[(size_t)s * HC + c0];
    float* od = &g_agg[(size_t)d * HC + c0];
    float4 v0 = *(const float4*)xs;
    float4 v1 = *(const float4*)(xs + 4);
    red_add_v4(od,     v0.x * coef, v0.y * coef, v0.z * coef, v0.w * coef);
    red_add_v4(od + 4, v1.x * coef, v1.y * coef, v1.z * coef, v1.w * coef);
}

// out = g_agg + b (outp==nullptr -> in place into g_agg). float4 indexed.
__global__ void k_bias(const float* __restrict__ b, float* __restrict__ outp) {
    int i = blockIdx.x * blockDim.x + threadIdx.x;  // NN*HC/4 threads exactly
    float4 v = ((const float4*)g_agg)[i];
    int col4 = (i * 4) & 255;
    float4 bb = *(const float4*)&b[col4];
    v.x += bb.x; v.y += bb.y; v.z += bb.z; v.w += bb.w;
    if (outp) ((float4*)outp)[i] = v;
    else      ((float4*)g_agg)[i] = v;
}

// ---------------- launch ---------------------------------------------------
extern "C" void kernel_launch(void* const* d_in, const int* in_sizes, int n_in,
                              void* d_out, int out_size) {
    const float* x       = (const float*)d_in[0];
    const int*   ei      = (const int*)d_in[1];
    const int*   src     = ei;
    const int*   dst     = ei + NE;
    const float* eattr   = (const float*)d_in[3];
    const float* eatten  = (const float*)d_in[4];
    const float* W1      = (const float*)d_in[5];
    const float* a_src1  = (const float*)d_in[6];
    const float* a_dst1  = (const float*)d_in[7];
    const float* W_e1    = (const float*)d_in[8];
    const float* a_e1    = (const float*)d_in[9];
    const float* b1      = (const float*)d_in[10];
    const float* W2      = (const float*)d_in[11];
    const float* a_src2  = (const float*)d_in[12];
    const float* a_dst2  = (const float*)d_in[13];
    const float* W_e2    = (const float*)d_in[14];
    const float* a_e2    = (const float*)d_in[15];
    const float* b2      = (const float*)d_in[16];

    float* out    = (float*)d_out;
    float* h_out  = out;                 // [NN, 256]
    float* w1_out = out + (size_t)NN * HC;
    float* w2_out = w1_out + (size_t)NE * NH;

    const int EB = (NE + 255) / 256;              // 2500
    const int AGGB = (NE * 32) / 256;             // 80000
    const int Z4 = (NN * HC / 4) / 256;           // 5000
    const int NB = (NN * NH + 255) / 256;         // 313
    dim3 gemm_grid((NN + 63) / 64, NH);

    k_ce<<<1, 256>>>(W_e1, a_e1, W_e2, a_e2);

    // ---- layer 1 ----
    k_init_nodes<<<NB, 256>>>();
    k_zero_agg<<<Z4, 256>>>();
    k_gemm<<<gemm_grid, 256>>>(x, W1, a_src1, a_dst1, 128);
    k_edge_alpha<<<EB, 256>>>(src, dst, eattr, 0);
    k_edge_expsum<<<EB, 256>>>(dst);
    k_edge_agg<<<AGGB, 256>>>(src, dst, eatten, w1_out);
    k_bias<<<Z4, 256>>>(b1, nullptr);   // g_agg := h1

    // ---- layer 2 ----
    k_init_nodes<<<NB, 256>>>();
    k_gemm<<<gemm_grid, 256>>>(nullptr /*g_agg*/, W2, a_src2, a_dst2, 256);
    k_zero_agg<<<Z4, 256>>>();          // after GEMM consumed h1
    k_edge_alpha<<<EB, 256>>>(src, dst, eattr, 4);
    k_edge_expsum<<<EB, 256>>>(dst);
    k_edge_agg<<<AGGB, 256>>>(src, dst, eatten, w2_out);
    k_bias<<<Z4, 256>>>(b2, h_out);     // final h
}

// round 4
// speedup vs baseline: 1.4777x; 1.4777x over previous
#include <cuda_runtime.h>
#include <cstdint>

#define NN 20000
#define NE 640000
#define HC 256      // H * C = 4 * 64
#define NH 4
#define FULLM 0xffffffffu

// ---------------- scratch (static device globals; no allocation) ----------
__device__ float g_xh[NN * HC];        // per-layer transformed node features
__device__ float g_agg[NN * HC];       // h between layers (layer-1 output)
__device__ float g_asrc[NN * NH];
__device__ float g_adst[NN * NH];
__device__ float g_alpha_s[NE * NH];   // raw alpha in CSR (dst-sorted) order
__device__ float g_ce[2 * NH];         // per-head edge-attr coefficient, both layers
// CSR
__device__ int g_deg[NN];
__device__ int g_rowstart[NN + 1];
__device__ int g_cursor[NN];
__device__ int g_esrc_s[NE];
__device__ int g_eid_s[NE];
__device__ int g_edst_s[NE];

// ---------------- tiny setup kernels --------------------------------------
// ce[h] = sum_c W_e[h*64+c] * a_e[h*64+c]  (edge_attr is [E,1])
__global__ void k_ce(const float* __restrict__ We1, const float* __restrict__ ae1,
                     const float* __restrict__ We2, const float* __restrict__ ae2) {
    __shared__ float s1[256], s2[256];
    int t = threadIdx.x;
    s1[t] = We1[t] * ae1[t];
    s2[t] = We2[t] * ae2[t];
    __syncthreads();
    if (t < 8) {
        const float* s = (t >= 4) ? s2 : s1;
        int h = t & 3;
        float sum = 0.f;
#pragma unroll
        for (int c = 0; c < 64; c++) sum += s[h * 64 + c];
        g_ce[t] = sum;
    }
}

// ---------------- CSR build ------------------------------------------------
__global__ void k_zero_deg() {
    int i = blockIdx.x * blockDim.x + threadIdx.x;
    if (i < NN) g_deg[i] = 0;
}

__global__ void k_hist(const int* __restrict__ dst) {
    int e = blockIdx.x * blockDim.x + threadIdx.x;
    if (e < NE) atomicAdd(&g_deg[dst[e]], 1);
}

// exclusive scan of g_deg -> g_rowstart / g_cursor. One block, 1024 threads,
// thread t handles 20 contiguous entries (1000 * 20 = 20000).
__global__ void k_scan() {
    __shared__ int wsum[32];
    int t = threadIdx.x;
    int loc[20];
    int tot = 0;
    if (t < 1000) {
        int base = t * 20;
#pragma unroll
        for (int i = 0; i < 20; i++) { loc[i] = tot; tot += g_deg[base + i]; }
    }
    int lane = t & 31, w = t >> 5;
    int v = tot;
#pragma unroll
    for (int o = 1; o < 32; o <<= 1) {
        int u = __shfl_up_sync(FULLM, v, o);
        if (lane >= o) v += u;
    }
    if (lane == 31) wsum[w] = v;
    __syncthreads();
    if (w == 0) {
        int s = wsum[lane];
#pragma unroll
        for (int o = 1; o < 32; o <<= 1) {
            int u = __shfl_up_sync(FULLM, s, o);
            if (lane >= o) s += u;
        }
        wsum[lane] = s;
    }
    __syncthreads();
    int excl = v - tot + (w ? wsum[w - 1] : 0);
    if (t < 1000) {
        int base = t * 20;
#pragma unroll
        for (int i = 0; i < 20; i++) {
            int r = excl + loc[i];
            g_rowstart[base + i] = r;
            g_cursor[base + i] = r;
        }
        if (t == 999) g_rowstart[NN] = excl + tot;
    }
}

__global__ void k_scatter(const int* __restrict__ src, const int* __restrict__ dst) {
    int e = blockIdx.x * blockDim.x + threadIdx.x;
    if (e >= NE) return;
    int d = dst[e];
    int pos = atomicAdd(&g_cursor[d], 1);
    g_esrc_s[pos] = src[e];
    g_eid_s[pos] = e;
    g_edst_s[pos] = d;
}

// ---------------- GEMM: xh = X @ W, fused alpha_src/alpha_dst -------------
// grid: (ceil(NN/64), 4 heads), block 256. Tile 64x64, BK=32, 4x4 per thread.
// X==nullptr means read from g_agg (layer 2 input).
__global__ void k_gemm(const float* __restrict__ X, const float* __restrict__ W,
                       const float* __restrict__ a_src, const float* __restrict__ a_dst,
                       int K) {
    __shared__ float As[32][68];   // transposed: As[k][m]
    __shared__ float Bs[32][68];   // Bs[k][n]
    const float* Xp = X ? X : g_agg;

    int tid = threadIdx.x;
    int r0 = blockIdx.x * 64;
    int head = blockIdx.y;
    int c0 = head * 64;
    int tx = tid & 15, ty = tid >> 4;
    int m0 = ty * 4, n0 = tx * 4;

    float acc[4][4] = {};

    for (int kk = 0; kk < K; kk += 32) {
#pragma unroll
        for (int j = 0; j < 2; j++) {
            int i = tid + 256 * j;
            int row = i >> 3;
            int kq = i & 7;
            float4 v = make_float4(0.f, 0.f, 0.f, 0.f);
            int gr = r0 + row;
            if (gr < NN) v = *(const float4*)&Xp[(size_t)gr * K + kk + kq * 4];
            As[kq * 4 + 0][row] = v.x;
            As[kq * 4 + 1][row] = v.y;
            As[kq * 4 + 2][row] = v.z;
            As[kq * 4 + 3][row] = v.w;
        }
#pragma unroll
        for (int j = 0; j < 2; j++) {
            int i = tid + 256 * j;
            int kr = i >> 4;
            int cq = i & 15;
            float4 v = *(const float4*)&W[(size_t)(kk + kr) * HC + c0 + cq * 4];
            *(float4*)&Bs[kr][cq * 4] = v;
        }
        __syncthreads();
#pragma unroll
        for (int k = 0; k < 32; k++) {
            float4 av = *(float4*)&As[k][m0];
            float4 bv = *(float4*)&Bs[k][n0];
            float ar[4] = {av.x, av.y, av.z, av.w};
            float br[4] = {bv.x, bv.y, bv.z, bv.w};
#pragma unroll
            for (int i = 0; i < 4; i++)
#pragma unroll
                for (int j = 0; j < 4; j++)
                    acc[i][j] = fmaf(ar[i], br[j], acc[i][j]);
        }
        __syncthreads();
    }

    float4 as4 = *(const float4*)&a_src[head * 64 + n0];
    float4 ad4 = *(const float4*)&a_dst[head * 64 + n0];

#pragma unroll
    for (int i = 0; i < 4; i++) {
        int gr = r0 + m0 + i;
        float ps = acc[i][0] * as4.x + acc[i][1] * as4.y + acc[i][2] * as4.z + acc[i][3] * as4.w;
        float pd = acc[i][0] * ad4.x + acc[i][1] * ad4.y + acc[i][2] * ad4.z + acc[i][3] * ad4.w;
#pragma unroll
        for (int o = 8; o; o >>= 1) {
            ps += __shfl_down_sync(FULLM, ps, o, 16);
            pd += __shfl_down_sync(FULLM, pd, o, 16);
        }
        if (gr < NN) {
            *(float4*)&g_xh[(size_t)gr * HC + c0 + n0] =
                make_float4(acc[i][0], acc[i][1], acc[i][2], acc[i][3]);
            if (tx == 0) {
                g_asrc[gr * NH + head] = ps;
                g_adst[gr * NH + head] = pd;
            }
        }
    }
}

// ---------------- edge logits (CSR order, coalesced writes) ----------------
__global__ void k_alpha(const float* __restrict__ eattr, int ce_off) {
    int i = blockIdx.x * blockDim.x + threadIdx.x;
    if (i >= NE) return;
    int s = g_esrc_s[i];
    int d = g_edst_s[i];
    int orig = g_eid_s[i];
    float4 as = *(const float4*)&g_asrc[s * 4];
    float4 ad = *(const float4*)&g_adst[d * 4];
    float ea = __ldg(&eattr[orig]);
    float a0 = as.x + ad.x + ea * g_ce[ce_off + 0];
    float a1 = as.y + ad.y + ea * g_ce[ce_off + 1];
    float a2 = as.z + ad.z + ea * g_ce[ce_off + 2];
    float a3 = as.w + ad.w + ea * g_ce[ce_off + 3];
    a0 = a0 >= 0.f ? a0 : 0.2f * a0;
    a1 = a1 >= 0.f ? a1 : 0.2f * a1;
    a2 = a2 >= 0.f ? a2 : 0.2f * a2;
    a3 = a3 >= 0.f ? a3 : 0.2f * a3;
    *(float4*)&g_alpha_s[(size_t)i * 4] = make_float4(a0, a1, a2, a3);
}

// ---------------- fused softmax + aggregation: one warp per node -----------
// Computes per-node segment max/sum, normalized weights (scattered to wout in
// original edge order), gathers xh[src] and writes out[node] = sum + bias.
// outp==nullptr -> write g_agg (layer-1 intermediate).
__global__ void k_agg(const float* __restrict__ atten, const float* __restrict__ bias,
                      float* __restrict__ wout, float* __restrict__ outp) {
    int n = blockIdx.x * 8 + (threadIdx.x >> 5);
    int lane = threadIdx.x & 31;
    if (n >= NN) return;
    int r0 = g_rowstart[n], r1 = g_rowstart[n + 1];

    // pass 1: per-head max
    float m0 = -3.4e38f, m1 = -3.4e38f, m2 = -3.4e38f, m3 = -3.4e38f;
    for (int j = r0 + lane; j < r1; j += 32) {
        float4 a = *(const float4*)&g_alpha_s[(size_t)j * 4];
        m0 = fmaxf(m0, a.x); m1 = fmaxf(m1, a.y);
        m2 = fmaxf(m2, a.z); m3 = fmaxf(m3, a.w);
    }
#pragma unroll
    for (int o = 16; o; o >>= 1) {
        m0 = fmaxf(m0, __shfl_xor_sync(FULLM, m0, o));
        m1 = fmaxf(m1, __shfl_xor_sync(FULLM, m1, o));
        m2 = fmaxf(m2, __shfl_xor_sync(FULLM, m2, o));
        m3 = fmaxf(m3, __shfl_xor_sync(FULLM, m3, o));
    }

    // pass 2: per-head exp-sum
    float s0 = 0.f, s1 = 0.f, s2 = 0.f, s3 = 0.f;
    for (int j = r0 + lane; j < r1; j += 32) {
        float4 a = *(const float4*)&g_alpha_s[(size_t)j * 4];
        s0 += __expf(a.x - m0); s1 += __expf(a.y - m1);
        s2 += __expf(a.z - m2); s3 += __expf(a.w - m3);
    }
#pragma unroll
    for (int o = 16; o; o >>= 1) {
        s0 += __shfl_xor_sync(FULLM, s0, o);
        s1 += __shfl_xor_sync(FULLM, s1, o);
        s2 += __shfl_xor_sync(FULLM, s2, o);
        s3 += __shfl_xor_sync(FULLM, s3, o);
    }
    float i0 = 1.f / (s0 + 1e-16f), i1 = 1.f / (s1 + 1e-16f);
    float i2 = 1.f / (s2 + 1e-16f), i3 = 1.f / (s3 + 1e-16f);

    // pass 3: sequential over edges, whole warp cooperates on the gather
    float acc0 = 0.f, acc1 = 0.f, acc2 = 0.f, acc3 = 0.f;
    float acc4 = 0.f, acc5 = 0.f, acc6 = 0.f, acc7 = 0.f;
    int h = lane >> 3;
    int c0 = lane * 8;
    float mh = (h == 0) ? m0 : (h == 1) ? m1 : (h == 2) ? m2 : m3;
    float ih = (h == 0) ? i0 : (h == 1) ? i1 : (h == 2) ? i2 : i3;
    float ml = (lane == 0) ? m0 : (lane == 1) ? m1 : (lane == 2) ? m2 : m3;
    float il = (lane == 0) ? i0 : (lane == 1) ? i1 : (lane == 2) ? i2 : i3;

    for (int j = r0; j < r1; j++) {
        int s = g_esrc_s[j];                       // broadcast
        int orig = g_eid_s[j];                     // broadcast
        float4 a = *(const float4*)&g_alpha_s[(size_t)j * 4];
        float at = __ldg(&atten[orig]);            // broadcast gather
        if (lane < 4) {
            float av = (lane == 0) ? a.x : (lane == 1) ? a.y : (lane == 2) ? a.z : a.w;
            wout[(size_t)orig * 4 + lane] = __expf(av - ml) * il;
        }
        float ah = (h == 0) ? a.x : (h == 1) ? a.y : (h == 2) ? a.z : a.w;
        float coef = __expf(ah - mh) * ih * at;
        const float4* xs = (const float4*)&g_xh[(size_t)s * HC + c0];
        float4 v0 = xs[0];
        float4 v1 = xs[1];
        acc0 = fmaf(v0.x, coef, acc0); acc1 = fmaf(v0.y, coef, acc1);
        acc2 = fmaf(v0.z, coef, acc2); acc3 = fmaf(v0.w, coef, acc3);
        acc4 = fmaf(v1.x, coef, acc4); acc5 = fmaf(v1.y, coef, acc5);
        acc6 = fmaf(v1.z, coef, acc6); acc7 = fmaf(v1.w, coef, acc7);
    }

    float4 b0 = *(const float4*)&bias[c0];
    float4 b1 = *(const float4*)&bias[c0 + 4];
    float* op = outp ? &outp[(size_t)n * HC + c0] : &g_agg[(size_t)n * HC + c0];
    *(float4*)op = make_float4(acc0 + b0.x, acc1 + b0.y, acc2 + b0.z, acc3 + b0.w);
    *(float4*)(op + 4) = make_float4(acc4 + b1.x, acc5 + b1.y, acc6 + b1.z, acc7 + b1.w);
}

// ---------------- launch ---------------------------------------------------
extern "C" void kernel_launch(void* const* d_in, const int* in_sizes, int n_in,
                              void* d_out, int out_size) {
    const float* x       = (const float*)d_in[0];
    const int*   ei      = (const int*)d_in[1];
    const int*   src     = ei;
    const int*   dst     = ei + NE;
    const float* eattr   = (const float*)d_in[3];
    const float* eatten  = (const float*)d_in[4];
    const float* W1      = (const float*)d_in[5];
    const float* a_src1  = (const float*)d_in[6];
    const float* a_dst1  = (const float*)d_in[7];
    const float* W_e1    = (const float*)d_in[8];
    const float* a_e1    = (const float*)d_in[9];
    const float* b1      = (const float*)d_in[10];
    const float* W2      = (const float*)d_in[11];
    const float* a_src2  = (const float*)d_in[12];
    const float* a_dst2  = (const float*)d_in[13];
    const float* W_e2    = (const float*)d_in[14];
    const float* a_e2    = (const float*)d_in[15];
    const float* b2      = (const float*)d_in[16];

    float* out    = (float*)d_out;
    float* h_out  = out;                        // [NN, 256]
    float* w1_out = out + (size_t)NN * HC;      // [NE, 4]
    float* w2_out = w1_out + (size_t)NE * NH;   // [NE, 4]

    const int EB = (NE + 255) / 256;            // 2500
    const int NB = (NN + 255) / 256;            // 79
    const int AB = NN / 8;                      // 2500 (8 warps/block, warp/node)
    dim3 gemm_grid((NN + 63) / 64, NH);

    k_ce<<<1, 256>>>(W_e1, a_e1, W_e2, a_e2);

    // ---- CSR build (shared by both layers) ----
    k_zero_deg<<<NB, 256>>>();
    k_hist<<<EB, 256>>>(dst);
    k_scan<<<1, 1024>>>();
    k_scatter<<<EB, 256>>>(src, dst);

    // ---- layer 1 ----
    k_gemm<<<gemm_grid, 256>>>(x, W1, a_src1, a_dst1, 128);
    k_alpha<<<EB, 256>>>(eattr, 0);
    k_agg<<<AB, 256>>>(eatten, b1, w1_out, nullptr);   // -> g_agg

    // ---- layer 2 ----
    k_gemm<<<gemm_grid, 256>>>(nullptr /*g_agg*/, W2, a_src2, a_dst2, 256);
    k_alpha<<<EB, 256>>>(eattr, 4);
    k_agg<<<AB, 256>>>(eatten, b2, w2_out, h_out);
}

// round 5
// speedup vs baseline: 1.5347x; 1.0386x over previous
#include <cuda_runtime.h>
#include <cstdint>

#define NN 20000
#define NE 640000
#define HC 256      // H * C = 4 * 64
#define NH 4
#define FULLM 0xffffffffu

// ---------------- scratch (static device globals; no allocation) ----------
__device__ float g_xh[NN * HC];        // per-layer transformed node features
__device__ float g_agg[NN * HC];       // h between layers (layer-1 output)
__device__ float g_asrc[NN * NH];
__device__ float g_adst[NN * NH];
__device__ float g_alpha_s[NE * NH];   // PARTIAL logits (asrc + ce*eattr) in CSR order
__device__ float g_ce[2 * NH];         // per-head edge-attr coefficient, both layers
// CSR
__device__ int g_deg[NN];
__device__ int g_rowstart[NN + 1];
__device__ int g_cursor[NN];
__device__ int g_esrc_s[NE];
__device__ int g_eid_s[NE];

// ---------------- tiny setup kernels --------------------------------------
__global__ void k_ce(const float* __restrict__ We1, const float* __restrict__ ae1,
                     const float* __restrict__ We2, const float* __restrict__ ae2) {
    __shared__ float s1[256], s2[256];
    int t = threadIdx.x;
    s1[t] = We1[t] * ae1[t];
    s2[t] = We2[t] * ae2[t];
    __syncthreads();
    if (t < 8) {
        const float* s = (t >= 4) ? s2 : s1;
        int h = t & 3;
        float sum = 0.f;
#pragma unroll
        for (int c = 0; c < 64; c++) sum += s[h * 64 + c];
        g_ce[t] = sum;
    }
}

// ---------------- CSR build ------------------------------------------------
__global__ void k_zero_deg() {
    int i = blockIdx.x * blockDim.x + threadIdx.x;
    if (i < NN) g_deg[i] = 0;
}

__global__ void k_hist(const int* __restrict__ dst) {
    int e = blockIdx.x * blockDim.x + threadIdx.x;
    if (e < NE) atomicAdd(&g_deg[dst[e]], 1);
}

// exclusive scan of g_deg -> g_rowstart / g_cursor. One block, 1024 threads.
// Coalesced: stage through 80 KB dynamic shared memory.
__global__ void k_scan() {
    extern __shared__ int sdeg[];       // NN ints
    __shared__ int wsum[32];
    int t = threadIdx.x;

    for (int i = t; i < NN; i += 1024) sdeg[i] = g_deg[i];
    __syncthreads();

    int loc[20];
    int tot = 0;
    if (t < 1000) {
        int base = t * 20;
#pragma unroll
        for (int i = 0; i < 20; i++) { loc[i] = tot; tot += sdeg[base + i]; }
    }
    int lane = t & 31, w = t >> 5;
    int v = tot;
#pragma unroll
    for (int o = 1; o < 32; o <<= 1) {
        int u = __shfl_up_sync(FULLM, v, o);
        if (lane >= o) v += u;
    }
    if (lane == 31) wsum[w] = v;
    __syncthreads();
    if (w == 0) {
        int s = wsum[lane];
#pragma unroll
        for (int o = 1; o < 32; o <<= 1) {
            int u = __shfl_up_sync(FULLM, s, o);
            if (lane >= o) s += u;
        }
        wsum[lane] = s;
    }
    __syncthreads();
    int excl = v - tot + (w ? wsum[w - 1] : 0);
    if (t < 1000) {
        int base = t * 20;
#pragma unroll
        for (int i = 0; i < 20; i++) sdeg[base + i] = excl + loc[i];
    }
    __syncthreads();
    for (int i = t; i < NN; i += 1024) {
        int r = sdeg[i];
        g_rowstart[i] = r;
        g_cursor[i] = r;
    }
    if (t == 0) g_rowstart[NN] = NE;
}

__global__ void k_scatter(const int* __restrict__ src, const int* __restrict__ dst) {
    int e = blockIdx.x * blockDim.x + threadIdx.x;
    if (e >= NE) return;
    int d = dst[e];
    int pos = atomicAdd(&g_cursor[d], 1);
    g_esrc_s[pos] = src[e];
    g_eid_s[pos] = e;
}

// ---------------- GEMM: xh = X @ W, fused alpha_src/alpha_dst -------------
// grid: (ceil(NN/128), 4 heads), 128 threads. Tile 128x64, BK=16, 8x8/thread.
// Thread (tx,ty), tx=tid&7, ty=tid>>3.
// rows: ty*4+{0..3} and 64+ty*4+{0..3}; cols: tx*4+{0..3} and 32+tx*4+{0..3}.
__global__ void __launch_bounds__(128)
k_gemm(const float* __restrict__ X, const float* __restrict__ W,
       const float* __restrict__ a_src, const float* __restrict__ a_dst, int K) {
    __shared__ __align__(16) float As[16][132];   // As[k][m], padded
    __shared__ __align__(16) float Bs[16][68];    // Bs[k][n]
    const float* Xp = X ? X : g_agg;

    int tid = threadIdx.x;
    int tx = tid & 7, ty = tid >> 3;
    int r0 = blockIdx.x * 128;
    int head = blockIdx.y;
    int c0 = head * 64;

    float acc[8][8] = {};

    for (int kk = 0; kk < K; kk += 16) {
        // load A tile 128x16 (4 float4 per thread), transposed into As[k][m]
#pragma unroll
        for (int l = 0; l < 4; l++) {
            int i = tid + 128 * l;      // 0..511
            int row = i >> 2;
            int kq = i & 3;
            float4 v = make_float4(0.f, 0.f, 0.f, 0.f);
            int gr = r0 + row;
            if (gr < NN) v = *(const float4*)&Xp[(size_t)gr * K + kk + kq * 4];
            As[kq * 4 + 0][row] = v.x;
            As[kq * 4 + 1][row] = v.y;
            As[kq * 4 + 2][row] = v.z;
            As[kq * 4 + 3][row] = v.w;
        }
        // load B tile 16x64 (2 float4 per thread)
#pragma unroll
        for (int l = 0; l < 2; l++) {
            int i = tid + 128 * l;      // 0..255
            int kr = i >> 4;
            int cq = i & 15;
            float4 v = *(const float4*)&W[(size_t)(kk + kr) * HC + c0 + cq * 4];
            *(float4*)&Bs[kr][cq * 4] = v;
        }
        __syncthreads();
#pragma unroll
        for (int k = 0; k < 16; k++) {
            float4 a0 = *(float4*)&As[k][ty * 4];
            float4 a1 = *(float4*)&As[k][64 + ty * 4];
            float4 b0 = *(float4*)&Bs[k][tx * 4];
            float4 b1 = *(float4*)&Bs[k][32 + tx * 4];
            float ar[8] = {a0.x, a0.y, a0.z, a0.w, a1.x, a1.y, a1.z, a1.w};
            float br[8] = {b0.x, b0.y, b0.z, b0.w, b1.x, b1.y, b1.z, b1.w};
#pragma unroll
            for (int i = 0; i < 8; i++)
#pragma unroll
                for (int j = 0; j < 8; j++)
                    acc[i][j] = fmaf(ar[i], br[j], acc[i][j]);
        }
        __syncthreads();
    }

    // epilogue: per-row dot with a_src/a_dst over my 8 cols, reduce over tx (8)
    float4 as0 = *(const float4*)&a_src[head * 64 + tx * 4];
    float4 as1 = *(const float4*)&a_src[head * 64 + 32 + tx * 4];
    float4 ad0 = *(const float4*)&a_dst[head * 64 + tx * 4];
    float4 ad1 = *(const float4*)&a_dst[head * 64 + 32 + tx * 4];
    float asv[8] = {as0.x, as0.y, as0.z, as0.w, as1.x, as1.y, as1.z, as1.w};
    float adv[8] = {ad0.x, ad0.y, ad0.z, ad0.w, ad1.x, ad1.y, ad1.z, ad1.w};

#pragma unroll
    for (int i = 0; i < 8; i++) {
        int gr = r0 + ((i < 4) ? (ty * 4 + i) : (64 + ty * 4 + i - 4));
        float ps = 0.f, pd = 0.f;
#pragma unroll
        for (int j = 0; j < 8; j++) {
            ps = fmaf(acc[i][j], asv[j], ps);
            pd = fmaf(acc[i][j], adv[j], pd);
        }
#pragma unroll
        for (int o = 4; o; o >>= 1) {
            ps += __shfl_down_sync(FULLM, ps, o, 8);
            pd += __shfl_down_sync(FULLM, pd, o, 8);
        }
        if (gr < NN) {
            *(float4*)&g_xh[(size_t)gr * HC + c0 + tx * 4] =
                make_float4(acc[i][0], acc[i][1], acc[i][2], acc[i][3]);
            *(float4*)&g_xh[(size_t)gr * HC + c0 + 32 + tx * 4] =
                make_float4(acc[i][4], acc[i][5], acc[i][6], acc[i][7]);
            if (tx == 0) {
                g_asrc[gr * NH + head] = ps;
                g_adst[gr * NH + head] = pd;
            }
        }
    }
}

// ---------------- edge partial logits (CSR order, coalesced writes) --------
// partial = asrc[src] + ce * eattr.  (adst + leaky applied in k_agg)
__global__ void k_alpha(const float* __restrict__ eattr, int ce_off) {
    int i = blockIdx.x * blockDim.x + threadIdx.x;
    if (i >= NE) return;
    int s = g_esrc_s[i];
    int orig = g_eid_s[i];
    float4 as = *(const float4*)&g_asrc[s * 4];
    float ea = __ldg(&eattr[orig]);
    float4 p;
    p.x = as.x + ea * g_ce[ce_off + 0];
    p.y = as.y + ea * g_ce[ce_off + 1];
    p.z = as.z + ea * g_ce[ce_off + 2];
    p.w = as.w + ea * g_ce[ce_off + 3];
    *(float4*)&g_alpha_s[(size_t)i * 4] = p;
}

__device__ __forceinline__ float lrelu(float v) { return v >= 0.f ? v : 0.2f * v; }

// ---------------- fused softmax + aggregation: one warp per node -----------
__global__ void k_agg(const float* __restrict__ atten, const float* __restrict__ bias,
                      float* __restrict__ wout, float* __restrict__ outp) {
    int n = blockIdx.x * 8 + (threadIdx.x >> 5);
    int lane = threadIdx.x & 31;
    if (n >= NN) return;
    int r0 = g_rowstart[n], r1 = g_rowstart[n + 1];
    float4 ad = *(const float4*)&g_adst[n * 4];

    // pass 1: online per-head (max, expsum)
    float m0 = -3.4e38f, m1 = -3.4e38f, m2 = -3.4e38f, m3 = -3.4e38f;
    float s0 = 0.f, s1 = 0.f, s2 = 0.f, s3 = 0.f;
    for (int j = r0 + lane; j < r1; j += 32) {
        float4 p = *(const float4*)&g_alpha_s[(size_t)j * 4];
        float a0 = lrelu(p.x + ad.x), a1 = lrelu(p.y + ad.y);
        float a2 = lrelu(p.z + ad.z), a3 = lrelu(p.w + ad.w);
        float t;
        t = fmaxf(m0, a0); s0 = s0 * __expf(m0 - t) + __expf(a0 - t); m0 = t;
        t = fmaxf(m1, a1); s1 = s1 * __expf(m1 - t) + __expf(a1 - t); m1 = t;
        t = fmaxf(m2, a2); s2 = s2 * __expf(m2 - t) + __expf(a2 - t); m2 = t;
        t = fmaxf(m3, a3); s3 = s3 * __expf(m3 - t) + __expf(a3 - t); m3 = t;
    }
#pragma unroll
    for (int o = 16; o; o >>= 1) {
        float om, os, nm;
        om = __shfl_xor_sync(FULLM, m0, o); os = __shfl_xor_sync(FULLM, s0, o);
        nm = fmaxf(m0, om); s0 = s0 * __expf(m0 - nm) + os * __expf(om - nm); m0 = nm;
        om = __shfl_xor_sync(FULLM, m1, o); os = __shfl_xor_sync(FULLM, s1, o);
        nm = fmaxf(m1, om); s1 = s1 * __expf(m1 - nm) + os * __expf(om - nm); m1 = nm;
        om = __shfl_xor_sync(FULLM, m2, o); os = __shfl_xor_sync(FULLM, s2, o);
        nm = fmaxf(m2, om); s2 = s2 * __expf(m2 - nm) + os * __expf(om - nm); m2 = nm;
        om = __shfl_xor_sync(FULLM, m3, o); os = __shfl_xor_sync(FULLM, s3, o);
        nm = fmaxf(m3, om); s3 = s3 * __expf(m3 - nm) + os * __expf(om - nm); m3 = nm;
    }
    float i0 = 1.f / (s0 + 1e-16f), i1 = 1.f / (s1 + 1e-16f);
    float i2 = 1.f / (s2 + 1e-16f), i3 = 1.f / (s3 + 1e-16f);

    // pass 2: gather + accumulate; whole warp cooperates per edge
    float acc0 = 0.f, acc1 = 0.f, acc2 = 0.f, acc3 = 0.f;
    float acc4 = 0.f, acc5 = 0.f, acc6 = 0.f, acc7 = 0.f;
    int h = lane >> 3;
    int c0 = lane * 8;
    float mh = (h == 0) ? m0 : (h == 1) ? m1 : (h == 2) ? m2 : m3;
    float ih = (h == 0) ? i0 : (h == 1) ? i1 : (h == 2) ? i2 : i3;
    float adh = (h == 0) ? ad.x : (h == 1) ? ad.y : (h == 2) ? ad.z : ad.w;
    float ml = (lane == 0) ? m0 : (lane == 1) ? m1 : (lane == 2) ? m2 : m3;
    float il = (lane == 0) ? i0 : (lane == 1) ? i1 : (lane == 2) ? i2 : i3;
    float adl = (lane == 0) ? ad.x : (lane == 1) ? ad.y : (lane == 2) ? ad.z : ad.w;

    for (int j = r0; j < r1; j++) {
        int s = g_esrc_s[j];                       // broadcast
        int orig = g_eid_s[j];                     // broadcast
        float4 p = *(const float4*)&g_alpha_s[(size_t)j * 4];
        float at = __ldg(&atten[orig]);            // broadcast gather
        if (lane < 4) {
            float pl = (lane == 0) ? p.x : (lane == 1) ? p.y : (lane == 2) ? p.z : p.w;
            wout[(size_t)orig * 4 + lane] = __expf(lrelu(pl + adl) - ml) * il;
        }
        float ph = (h == 0) ? p.x : (h == 1) ? p.y : (h == 2) ? p.z : p.w;
        float coef = __expf(lrelu(ph + adh) - mh) * ih * at;
        const float4* xs = (const float4*)&g_xh[(size_t)s * HC + c0];
        float4 v0 = xs[0];
        float4 v1 = xs[1];
        acc0 = fmaf(v0.x, coef, acc0); acc1 = fmaf(v0.y, coef, acc1);
        acc2 = fmaf(v0.z, coef, acc2); acc3 = fmaf(v0.w, coef, acc3);
        acc4 = fmaf(v1.x, coef, acc4); acc5 = fmaf(v1.y, coef, acc5);
        acc6 = fmaf(v1.z, coef, acc6); acc7 = fmaf(v1.w, coef, acc7);
    }

    float4 b0 = *(const float4*)&bias[c0];
    float4 b1 = *(const float4*)&bias[c0 + 4];
    float* op = outp ? &outp[(size_t)n * HC + c0] : &g_agg[(size_t)n * HC + c0];
    *(float4*)op = make_float4(acc0 + b0.x, acc1 + b0.y, acc2 + b0.z, acc3 + b0.w);
    *(float4*)(op + 4) = make_float4(acc4 + b1.x, acc5 + b1.y, acc6 + b1.z, acc7 + b1.w);
}

// ---------------- launch ---------------------------------------------------
extern "C" void kernel_launch(void* const* d_in, const int* in_sizes, int n_in,
                              void* d_out, int out_size) {
    const float* x       = (const float*)d_in[0];
    const int*   ei      = (const int*)d_in[1];
    const int*   src     = ei;
    const int*   dst     = ei + NE;
    const float* eattr   = (const float*)d_in[3];
    const float* eatten  = (const float*)d_in[4];
    const float* W1      = (const float*)d_in[5];
    const float* a_src1  = (const float*)d_in[6];
    const float* a_dst1  = (const float*)d_in[7];
    const float* W_e1    = (const float*)d_in[8];
    const float* a_e1    = (const float*)d_in[9];
    const float* b1      = (const float*)d_in[10];
    const float* W2      = (const float*)d_in[11];
    const float* a_src2  = (const float*)d_in[12];
    const float* a_dst2  = (const float*)d_in[13];
    const float* W_e2    = (const float*)d_in[14];
    const float* a_e2    = (const float*)d_in[15];
    const float* b2      = (const float*)d_in[16];

    float* out    = (float*)d_out;
    float* h_out  = out;                        // [NN, 256]
    float* w1_out = out + (size_t)NN * HC;      // [NE, 4]
    float* w2_out = w1_out + (size_t)NE * NH;   // [NE, 4]

    const int EB = (NE + 255) / 256;            // 2500
    const int NB = (NN + 255) / 256;            // 79
    const int AB = NN / 8;                      // 2500 (8 warps/block, warp/node)
    dim3 gemm_grid((NN + 127) / 128, NH);

    static int scan_smem_set = 0;
    cudaFuncSetAttribute(k_scan, cudaFuncAttributeMaxDynamicSharedMemorySize, NN * 4);
    (void)scan_smem_set;

    k_ce<<<1, 256>>>(W_e1, a_e1, W_e2, a_e2);

    // ---- CSR build (shared by both layers) ----
    k_zero_deg<<<NB, 256>>>();
    k_hist<<<EB, 256>>>(dst);
    k_scan<<<1, 1024, NN * 4>>>();
    k_scatter<<<EB, 256>>>(src, dst);

    // ---- layer 1 ----
    k_gemm<<<gemm_grid, 128>>>(x, W1, a_src1, a_dst1, 128);
    k_alpha<<<EB, 256>>>(eattr, 0);
    k_agg<<<AB, 256>>>(eatten, b1, w1_out, nullptr);   // -> g_agg

    // ---- layer 2 ----
    k_gemm<<<gemm_grid, 128>>>(nullptr /*g_agg*/, W2, a_src2, a_dst2, 256);
    k_alpha<<<EB, 256>>>(eattr, 4);
    k_agg<<<AB, 256>>>(eatten, b2, w2_out, h_out);
}

// round 6
// speedup vs baseline: 1.9311x; 1.2583x over previous
#include <cuda_runtime.h>
#include <cstdint>

#define NN 20000
#define NE 640000
#define HC 256      // H * C = 4 * 64
#define NH 4
#define FULLM 0xffffffffu

// ---------------- scratch (static device globals; no allocation) ----------
__device__ float g_xh[NN * HC];        // per-layer transformed node features
__device__ float g_agg[NN * HC];       // h between layers (layer-1 output)
__device__ float g_asrc[NN * NH];
__device__ float g_adst[NN * NH];
__device__ float g_alpha_s[NE * NH];   // PARTIAL logits (asrc + ce*eattr) in CSR order
__device__ float g_ce[2 * NH];         // per-head edge-attr coefficient, both layers
// CSR
__device__ int g_deg[NN];
__device__ __align__(16) int g_rowstart[NN + 4];
__device__ int g_cursor[NN];
__device__ int g_esrc_s[NE];
__device__ int g_eid_s[NE];

// ---------------- tiny setup kernels --------------------------------------
__global__ void k_ce(const float* __restrict__ We1, const float* __restrict__ ae1,
                     const float* __restrict__ We2, const float* __restrict__ ae2) {
    __shared__ float s1[256], s2[256];
    int t = threadIdx.x;
    s1[t] = We1[t] * ae1[t];
    s2[t] = We2[t] * ae2[t];
    __syncthreads();
    if (t < 8) {
        const float* s = (t >= 4) ? s2 : s1;
        int h = t & 3;
        float sum = 0.f;
#pragma unroll
        for (int c = 0; c < 64; c++) sum += s[h * 64 + c];
        g_ce[t] = sum;
    }
}

// ---------------- CSR build ------------------------------------------------
__global__ void k_zero_deg() {
    int i = blockIdx.x * blockDim.x + threadIdx.x;
    if (i < NN) g_deg[i] = 0;
}

__global__ void k_hist(const int* __restrict__ dst) {
    int e = blockIdx.x * blockDim.x + threadIdx.x;
    if (e < NE) atomicAdd(&g_deg[dst[e]], 1);
}

// exclusive scan of g_deg -> g_rowstart / g_cursor. One block, 1024 threads.
// Vectorized staging through shared memory.
__global__ void k_scan() {
    extern __shared__ int sdeg[];       // NN ints
    __shared__ int wsum[32];
    int t = threadIdx.x;

    for (int i = t; i < NN / 4; i += 1024)
        ((int4*)sdeg)[i] = ((const int4*)g_deg)[i];
    __syncthreads();

    int loc[20];
    int tot = 0;
    if (t < 1000) {
        int base = t * 20;
#pragma unroll
        for (int i = 0; i < 20; i++) { loc[i] = tot; tot += sdeg[base + i]; }
    }
    int lane = t & 31, w = t >> 5;
    int v = tot;
#pragma unroll
    for (int o = 1; o < 32; o <<= 1) {
        int u = __shfl_up_sync(FULLM, v, o);
        if (lane >= o) v += u;
    }
    if (lane == 31) wsum[w] = v;
    __syncthreads();
    if (w == 0) {
        int s = wsum[lane];
#pragma unroll
        for (int o = 1; o < 32; o <<= 1) {
            int u = __shfl_up_sync(FULLM, s, o);
            if (lane >= o) s += u;
        }
        wsum[lane] = s;
    }
    __syncthreads();
    int excl = v - tot + (w ? wsum[w - 1] : 0);
    __syncthreads();
    if (t < 1000) {
        int base = t * 20;
#pragma unroll
        for (int i = 0; i < 20; i++) sdeg[base + i] = excl + loc[i];
    }
    __syncthreads();
    for (int i = t; i < NN / 4; i += 1024) {
        int4 r = ((const int4*)sdeg)[i];
        ((int4*)g_rowstart)[i] = r;
        ((int4*)g_cursor)[i] = r;
    }
    if (t == 0) g_rowstart[NN] = NE;
}

__global__ void k_scatter(const int* __restrict__ src, const int* __restrict__ dst) {
    int e = blockIdx.x * blockDim.x + threadIdx.x;
    if (e >= NE) return;
    int d = dst[e];
    int pos = atomicAdd(&g_cursor[d], 1);
    g_esrc_s[pos] = src[e];
    g_eid_s[pos] = e;
}

// ---------------- GEMM: xh = X @ W, fused alpha_src/alpha_dst -------------
__global__ void __launch_bounds__(128)
k_gemm(const float* __restrict__ X, const float* __restrict__ W,
       const float* __restrict__ a_src, const float* __restrict__ a_dst, int K) {
    __shared__ __align__(16) float As[16][132];   // As[k][m], padded
    __shared__ __align__(16) float Bs[16][68];    // Bs[k][n]
    const float* Xp = X ? X : g_agg;

    int tid = threadIdx.x;
    int tx = tid & 7, ty = tid >> 3;
    int r0 = blockIdx.x * 128;
    int head = blockIdx.y;
    int c0 = head * 64;

    float acc[8][8] = {};

    for (int kk = 0; kk < K; kk += 16) {
#pragma unroll
        for (int l = 0; l < 4; l++) {
            int i = tid + 128 * l;      // 0..511
            int row = i >> 2;
            int kq = i & 3;
            float4 v = make_float4(0.f, 0.f, 0.f, 0.f);
            int gr = r0 + row;
            if (gr < NN) v = *(const float4*)&Xp[(size_t)gr * K + kk + kq * 4];
            As[kq * 4 + 0][row] = v.x;
            As[kq * 4 + 1][row] = v.y;
            As[kq * 4 + 2][row] = v.z;
            As[kq * 4 + 3][row] = v.w;
        }
#pragma unroll
        for (int l = 0; l < 2; l++) {
            int i = tid + 128 * l;      // 0..255
            int kr = i >> 4;
            int cq = i & 15;
            float4 v = *(const float4*)&W[(size_t)(kk + kr) * HC + c0 + cq * 4];
            *(float4*)&Bs[kr][cq * 4] = v;
        }
        __syncthreads();
#pragma unroll
        for (int k = 0; k < 16; k++) {
            float4 a0 = *(float4*)&As[k][ty * 4];
            float4 a1 = *(float4*)&As[k][64 + ty * 4];
            float4 b0 = *(float4*)&Bs[k][tx * 4];
            float4 b1 = *(float4*)&Bs[k][32 + tx * 4];
            float ar[8] = {a0.x, a0.y, a0.z, a0.w, a1.x, a1.y, a1.z, a1.w};
            float br[8] = {b0.x, b0.y, b0.z, b0.w, b1.x, b1.y, b1.z, b1.w};
#pragma unroll
            for (int i = 0; i < 8; i++)
#pragma unroll
                for (int j = 0; j < 8; j++)
                    acc[i][j] = fmaf(ar[i], br[j], acc[i][j]);
        }
        __syncthreads();
    }

    float4 as0 = *(const float4*)&a_src[head * 64 + tx * 4];
    float4 as1 = *(const float4*)&a_src[head * 64 + 32 + tx * 4];
    float4 ad0 = *(const float4*)&a_dst[head * 64 + tx * 4];
    float4 ad1 = *(const float4*)&a_dst[head * 64 + 32 + tx * 4];
    float asv[8] = {as0.x, as0.y, as0.z, as0.w, as1.x, as1.y, as1.z, as1.w};
    float adv[8] = {ad0.x, ad0.y, ad0.z, ad0.w, ad1.x, ad1.y, ad1.z, ad1.w};

#pragma unroll
    for (int i = 0; i < 8; i++) {
        int gr = r0 + ((i < 4) ? (ty * 4 + i) : (64 + ty * 4 + i - 4));
        float ps = 0.f, pd = 0.f;
#pragma unroll
        for (int j = 0; j < 8; j++) {
            ps = fmaf(acc[i][j], asv[j], ps);
            pd = fmaf(acc[i][j], adv[j], pd);
        }
#pragma unroll
        for (int o = 4; o; o >>= 1) {
            ps += __shfl_down_sync(FULLM, ps, o, 8);
            pd += __shfl_down_sync(FULLM, pd, o, 8);
        }
        if (gr < NN) {
            *(float4*)&g_xh[(size_t)gr * HC + c0 + tx * 4] =
                make_float4(acc[i][0], acc[i][1], acc[i][2], acc[i][3]);
            *(float4*)&g_xh[(size_t)gr * HC + c0 + 32 + tx * 4] =
                make_float4(acc[i][4], acc[i][5], acc[i][6], acc[i][7]);
            if (tx == 0) {
                g_asrc[gr * NH + head] = ps;
                g_adst[gr * NH + head] = pd;
            }
        }
    }
}

// ---------------- edge partial logits (CSR order, coalesced writes) --------
__global__ void k_alpha(const float* __restrict__ eattr, int ce_off) {
    int i = blockIdx.x * blockDim.x + threadIdx.x;
    if (i >= NE) return;
    int s = g_esrc_s[i];
    int orig = g_eid_s[i];
    float4 as = *(const float4*)&g_asrc[s * 4];
    float ea = __ldg(&eattr[orig]);
    float4 p;
    p.x = as.x + ea * g_ce[ce_off + 0];
    p.y = as.y + ea * g_ce[ce_off + 1];
    p.z = as.z + ea * g_ce[ce_off + 2];
    p.w = as.w + ea * g_ce[ce_off + 3];
    *(float4*)&g_alpha_s[(size_t)i * 4] = p;
}

__device__ __forceinline__ float lrelu(float v) { return v >= 0.f ? v : 0.2f * v; }

// ---------------- fused softmax + aggregation: one warp per node -----------
// Pass 2 processes edges in warp-wide chunks of 32: lane-parallel metadata
// loads + wout ST.128, coefs/srcs staged in smem, then a tight gather loop
// with full memory-level parallelism.
__global__ void __launch_bounds__(256)
k_agg(const float* __restrict__ atten, const float* __restrict__ bias,
      float* __restrict__ wout, float* __restrict__ outp) {
    __shared__ float s_c[8][128];   // per-warp: 32 edges x 4 head-coefs
    __shared__ int   s_s[8][32];    // per-warp: 32 src ids
    int wrp = threadIdx.x >> 5;
    int n = blockIdx.x * 8 + wrp;
    int lane = threadIdx.x & 31;
    if (n >= NN) return;
    int r0 = g_rowstart[n], r1 = g_rowstart[n + 1];
    float4 ad = *(const float4*)&g_adst[n * 4];

    // pass 1: online per-head (max, expsum), lane-parallel
    float m0 = -3.4e38f, m1 = -3.4e38f, m2 = -3.4e38f, m3 = -3.4e38f;
    float s0 = 0.f, s1 = 0.f, s2 = 0.f, s3 = 0.f;
    for (int j = r0 + lane; j < r1; j += 32) {
        float4 p = *(const float4*)&g_alpha_s[(size_t)j * 4];
        float a0 = lrelu(p.x + ad.x), a1 = lrelu(p.y + ad.y);
        float a2 = lrelu(p.z + ad.z), a3 = lrelu(p.w + ad.w);
        float t;
        t = fmaxf(m0, a0); s0 = s0 * __expf(m0 - t) + __expf(a0 - t); m0 = t;
        t = fmaxf(m1, a1); s1 = s1 * __expf(m1 - t) + __expf(a1 - t); m1 = t;
        t = fmaxf(m2, a2); s2 = s2 * __expf(m2 - t) + __expf(a2 - t); m2 = t;
        t = fmaxf(m3, a3); s3 = s3 * __expf(m3 - t) + __expf(a3 - t); m3 = t;
    }
#pragma unroll
    for (int o = 16; o; o >>= 1) {
        float om, os, nm;
        om = __shfl_xor_sync(FULLM, m0, o); os = __shfl_xor_sync(FULLM, s0, o);
        nm = fmaxf(m0, om); s0 = s0 * __expf(m0 - nm) + os * __expf(om - nm); m0 = nm;
        om = __shfl_xor_sync(FULLM, m1, o); os = __shfl_xor_sync(FULLM, s1, o);
        nm = fmaxf(m1, om); s1 = s1 * __expf(m1 - nm) + os * __expf(om - nm); m1 = nm;
        om = __shfl_xor_sync(FULLM, m2, o); os = __shfl_xor_sync(FULLM, s2, o);
        nm = fmaxf(m2, om); s2 = s2 * __expf(m2 - nm) + os * __expf(om - nm); m2 = nm;
        om = __shfl_xor_sync(FULLM, m3, o); os = __shfl_xor_sync(FULLM, s3, o);
        nm = fmaxf(m3, om); s3 = s3 * __expf(m3 - nm) + os * __expf(om - nm); m3 = nm;
    }
    float i0 = 1.f / (s0 + 1e-16f), i1 = 1.f / (s1 + 1e-16f);
    float i2 = 1.f / (s2 + 1e-16f), i3 = 1.f / (s3 + 1e-16f);

    // pass 2: chunks of 32 edges
    float acc0 = 0.f, acc1 = 0.f, acc2 = 0.f, acc3 = 0.f;
    float acc4 = 0.f, acc5 = 0.f, acc6 = 0.f, acc7 = 0.f;
    int h = lane >> 3;
    int c0 = lane * 8;

    for (int base = r0; base < r1; base += 32) {
        int j = base + lane;
        bool valid = j < r1;
        int cnt = min(32, r1 - base);
        int s = valid ? g_esrc_s[j] : 0;
        int orig = valid ? g_eid_s[j] : 0;
        float4 p = valid ? *(const float4*)&g_alpha_s[(size_t)j * 4]
                         : make_float4(0.f, 0.f, 0.f, 0.f);
        float at = valid ? __ldg(&atten[orig]) : 0.f;
        // per-lane normalized weights for its edge (4 heads)
        float w0 = __expf(lrelu(p.x + ad.x) - m0) * i0;
        float w1 = __expf(lrelu(p.y + ad.y) - m1) * i1;
        float w2 = __expf(lrelu(p.z + ad.z) - m2) * i2;
        float w3 = __expf(lrelu(p.w + ad.w) - m3) * i3;
        if (valid)
            *(float4*)&wout[(size_t)orig * 4] = make_float4(w0, w1, w2, w3);
        __syncwarp();
        *(float4*)&s_c[wrp][lane * 4] = make_float4(w0 * at, w1 * at, w2 * at, w3 * at);
        s_s[wrp][lane] = s;
        __syncwarp();
        for (int k = 0; k < cnt; k++) {
            float coef = s_c[wrp][k * 4 + h];   // broadcast within head group
            int ss = s_s[wrp][k];               // broadcast
            const float4* xs = (const float4*)&g_xh[(size_t)ss * HC + c0];
            float4 v0 = xs[0];
            float4 v1 = xs[1];
            acc0 = fmaf(v0.x, coef, acc0); acc1 = fmaf(v0.y, coef, acc1);
            acc2 = fmaf(v0.z, coef, acc2); acc3 = fmaf(v0.w, coef, acc3);
            acc4 = fmaf(v1.x, coef, acc4); acc5 = fmaf(v1.y, coef, acc5);
            acc6 = fmaf(v1.z, coef, acc6); acc7 = fmaf(v1.w, coef, acc7);
        }
        __syncwarp();
    }

    float4 b0 = *(const float4*)&bias[c0];
    float4 b1 = *(const float4*)&bias[c0 + 4];
    float* op = outp ? &outp[(size_t)n * HC + c0] : &g_agg[(size_t)n * HC + c0];
    *(float4*)op = make_float4(acc0 + b0.x, acc1 + b0.y, acc2 + b0.z, acc3 + b0.w);
    *(float4*)(op + 4) = make_float4(acc4 + b1.x, acc5 + b1.y, acc6 + b1.z, acc7 + b1.w);
}

// ---------------- launch ---------------------------------------------------
extern "C" void kernel_launch(void* const* d_in, const int* in_sizes, int n_in,
                              void* d_out, int out_size) {
    const float* x       = (const float*)d_in[0];
    const int*   ei      = (const int*)d_in[1];
    const int*   src     = ei;
    const int*   dst     = ei + NE;
    const float* eattr   = (const float*)d_in[3];
    const float* eatten  = (const float*)d_in[4];
    const float* W1      = (const float*)d_in[5];
    const float* a_src1  = (const float*)d_in[6];
    const float* a_dst1  = (const float*)d_in[7];
    const float* W_e1    = (const float*)d_in[8];
    const float* a_e1    = (const float*)d_in[9];
    const float* b1      = (const float*)d_in[10];
    const float* W2      = (const float*)d_in[11];
    const float* a_src2  = (const float*)d_in[12];
    const float* a_dst2  = (const float*)d_in[13];
    const float* W_e2    = (const float*)d_in[14];
    const float* a_e2    = (const float*)d_in[15];
    const float* b2      = (const float*)d_in[16];

    float* out    = (float*)d_out;
    float* h_out  = out;                        // [NN, 256]
    float* w1_out = out + (size_t)NN * HC;      // [NE, 4]
    float* w2_out = w1_out + (size_t)NE * NH;   // [NE, 4]

    const int EB = (NE + 255) / 256;            // 2500
    const int NB = (NN + 255) / 256;            // 79
    const int AB = NN / 8;                      // 2500 (8 warps/block, warp/node)
    dim3 gemm_grid((NN + 127) / 128, NH);

    cudaFuncSetAttribute(k_scan, cudaFuncAttributeMaxDynamicSharedMemorySize, NN * 4);

    k_ce<<<1, 256>>>(W_e1, a_e1, W_e2, a_e2);

    // ---- CSR build (shared by both layers) ----
    k_zero_deg<<<NB, 256>>>();
    k_hist<<<EB, 256>>>(dst);
    k_scan<<<1, 1024, NN * 4>>>();
    k_scatter<<<EB, 256>>>(src, dst);

    // ---- layer 1 ----
    k_gemm<<<gemm_grid, 128>>>(x, W1, a_src1, a_dst1, 128);
    k_alpha<<<EB, 256>>>(eattr, 0);
    k_agg<<<AB, 256>>>(eatten, b1, w1_out, nullptr);   // -> g_agg

    // ---- layer 2 ----
    k_gemm<<<gemm_grid, 128>>>(nullptr /*g_agg*/, W2, a_src2, a_dst2, 256);
    k_alpha<<<EB, 256>>>(eattr, 4);
    k_agg<<<AB, 256>>>(eatten, b2, w2_out, h_out);
}

// round 7
// speedup vs baseline: 1.9581x; 1.0140x over previous
#include <cuda_runtime.h>
#include <cstdint>

#define NN 20000
#define NE 640000
#define HC 256      // H * C = 4 * 64
#define NH 4
#define FULLM 0xffffffffu
#define NEGINF -3.4e38f

// ---------------- scratch (static device globals; no allocation) ----------
__device__ float g_xh[NN * HC];        // per-layer transformed node features
__device__ float g_agg[NN * HC];       // h between layers (layer-1 output)
__device__ float g_asrc[NN * NH];
__device__ float g_adst[NN * NH];
__device__ float g_alpha_s[NE * NH];   // spill buffer for deg > 96 nodes only
__device__ float g_ce[2 * NH];         // per-head edge-attr coefficient, both layers
// CSR
__device__ int g_deg[NN];
__device__ __align__(16) int g_rowstart[NN + 4];
__device__ int g_cursor[NN];
__device__ int g_esrc_s[NE];
__device__ int g_eid_s[NE];

// ---------------- tiny setup kernels --------------------------------------
__global__ void k_ce(const float* __restrict__ We1, const float* __restrict__ ae1,
                     const float* __restrict__ We2, const float* __restrict__ ae2) {
    __shared__ float s1[256], s2[256];
    int t = threadIdx.x;
    s1[t] = We1[t] * ae1[t];
    s2[t] = We2[t] * ae2[t];
    __syncthreads();
    if (t < 8) {
        const float* s = (t >= 4) ? s2 : s1;
        int h = t & 3;
        float sum = 0.f;
#pragma unroll
        for (int c = 0; c < 64; c++) sum += s[h * 64 + c];
        g_ce[t] = sum;
    }
}

// ---------------- CSR build ------------------------------------------------
__global__ void k_zero_deg() {
    int i = blockIdx.x * blockDim.x + threadIdx.x;
    if (i < NN) g_deg[i] = 0;
}

__global__ void k_hist(const int* __restrict__ dst) {
    int e = blockIdx.x * blockDim.x + threadIdx.x;
    if (e < NE) atomicAdd(&g_deg[dst[e]], 1);
}

__global__ void k_scan() {
    extern __shared__ int sdeg[];       // NN ints
    __shared__ int wsum[32];
    int t = threadIdx.x;

    for (int i = t; i < NN / 4; i += 1024)
        ((int4*)sdeg)[i] = ((const int4*)g_deg)[i];
    __syncthreads();

    int loc[20];
    int tot = 0;
    if (t < 1000) {
        int base = t * 20;
#pragma unroll
        for (int i = 0; i < 20; i++) { loc[i] = tot; tot += sdeg[base + i]; }
    }
    int lane = t & 31, w = t >> 5;
    int v = tot;
#pragma unroll
    for (int o = 1; o < 32; o <<= 1) {
        int u = __shfl_up_sync(FULLM, v, o);
        if (lane >= o) v += u;
    }
    if (lane == 31) wsum[w] = v;
    __syncthreads();
    if (w == 0) {
        int s = wsum[lane];
#pragma unroll
        for (int o = 1; o < 32; o <<= 1) {
            int u = __shfl_up_sync(FULLM, s, o);
            if (lane >= o) s += u;
        }
        wsum[lane] = s;
    }
    __syncthreads();
    int excl = v - tot + (w ? wsum[w - 1] : 0);
    __syncthreads();
    if (t < 1000) {
        int base = t * 20;
#pragma unroll
        for (int i = 0; i < 20; i++) sdeg[base + i] = excl + loc[i];
    }
    __syncthreads();
    for (int i = t; i < NN / 4; i += 1024) {
        int4 r = ((const int4*)sdeg)[i];
        ((int4*)g_rowstart)[i] = r;
        ((int4*)g_cursor)[i] = r;
    }
    if (t == 0) g_rowstart[NN] = NE;
}

__global__ void k_scatter(const int* __restrict__ src, const int* __restrict__ dst) {
    int e = blockIdx.x * blockDim.x + threadIdx.x;
    if (e >= NE) return;
    int d = dst[e];
    int pos = atomicAdd(&g_cursor[d], 1);
    g_esrc_s[pos] = src[e];
    g_eid_s[pos] = e;
}

// ---------------- GEMM: xh = X @ W, fused alpha_src/alpha_dst -------------
__global__ void __launch_bounds__(128)
k_gemm(const float* __restrict__ X, const float* __restrict__ W,
       const float* __restrict__ a_src, const float* __restrict__ a_dst, int K) {
    __shared__ __align__(16) float As[16][132];
    __shared__ __align__(16) float Bs[16][68];
    const float* Xp = X ? X : g_agg;

    int tid = threadIdx.x;
    int tx = tid & 7, ty = tid >> 3;
    int r0 = blockIdx.x * 128;
    int head = blockIdx.y;
    int c0 = head * 64;

    float acc[8][8] = {};

    for (int kk = 0; kk < K; kk += 16) {
#pragma unroll
        for (int l = 0; l < 4; l++) {
            int i = tid + 128 * l;
            int row = i >> 2;
            int kq = i & 3;
            float4 v = make_float4(0.f, 0.f, 0.f, 0.f);
            int gr = r0 + row;
            if (gr < NN) v = *(const float4*)&Xp[(size_t)gr * K + kk + kq * 4];
            As[kq * 4 + 0][row] = v.x;
            As[kq * 4 + 1][row] = v.y;
            As[kq * 4 + 2][row] = v.z;
            As[kq * 4 + 3][row] = v.w;
        }
#pragma unroll
        for (int l = 0; l < 2; l++) {
            int i = tid + 128 * l;
            int kr = i >> 4;
            int cq = i & 15;
            float4 v = *(const float4*)&W[(size_t)(kk + kr) * HC + c0 + cq * 4];
            *(float4*)&Bs[kr][cq * 4] = v;
        }
        __syncthreads();
#pragma unroll
        for (int k = 0; k < 16; k++) {
            float4 a0 = *(float4*)&As[k][ty * 4];
            float4 a1 = *(float4*)&As[k][64 + ty * 4];
            float4 b0 = *(float4*)&Bs[k][tx * 4];
            float4 b1 = *(float4*)&Bs[k][32 + tx * 4];
            float ar[8] = {a0.x, a0.y, a0.z, a0.w, a1.x, a1.y, a1.z, a1.w};
            float br[8] = {b0.x, b0.y, b0.z, b0.w, b1.x, b1.y, b1.z, b1.w};
#pragma unroll
            for (int i = 0; i < 8; i++)
#pragma unroll
                for (int j = 0; j < 8; j++)
                    acc[i][j] = fmaf(ar[i], br[j], acc[i][j]);
        }
        __syncthreads();
    }

    float4 as0 = *(const float4*)&a_src[head * 64 + tx * 4];
    float4 as1 = *(const float4*)&a_src[head * 64 + 32 + tx * 4];
    float4 ad0 = *(const float4*)&a_dst[head * 64 + tx * 4];
    float4 ad1 = *(const float4*)&a_dst[head * 64 + 32 + tx * 4];
    float asv[8] = {as0.x, as0.y, as0.z, as0.w, as1.x, as1.y, as1.z, as1.w};
    float adv[8] = {ad0.x, ad0.y, ad0.z, ad0.w, ad1.x, ad1.y, ad1.z, ad1.w};

#pragma unroll
    for (int i = 0; i < 8; i++) {
        int gr = r0 + ((i < 4) ? (ty * 4 + i) : (64 + ty * 4 + i - 4));
        float ps = 0.f, pd = 0.f;
#pragma unroll
        for (int j = 0; j < 8; j++) {
            ps = fmaf(acc[i][j], asv[j], ps);
            pd = fmaf(acc[i][j], adv[j], pd);
        }
#pragma unroll
        for (int o = 4; o; o >>= 1) {
            ps += __shfl_down_sync(FULLM, ps, o, 8);
            pd += __shfl_down_sync(FULLM, pd, o, 8);
        }
        if (gr < NN) {
            *(float4*)&g_xh[(size_t)gr * HC + c0 + tx * 4] =
                make_float4(acc[i][0], acc[i][1], acc[i][2], acc[i][3]);
            *(float4*)&g_xh[(size_t)gr * HC + c0 + 32 + tx * 4] =
                make_float4(acc[i][4], acc[i][5], acc[i][6], acc[i][7]);
            if (tx == 0) {
                g_asrc[gr * NH + head] = ps;
                g_adst[gr * NH + head] = pd;
            }
        }
    }
}

__device__ __forceinline__ float lrelu(float v) { return v >= 0.f ? v : 0.2f * v; }

// ---------------- fused logits + softmax + aggregation ---------------------
// One warp per node. Phase 1 computes leaky-relu'd logits inline (asrc gather
// + ce*eattr + adst) with online max/expsum; logits/src/eid/atten for the
// first 3 chunks (96 edges) stay in registers, rest spills to g_alpha_s.
// Phase 2 writes normalized weights (wout, original edge order) and runs the
// warp-cooperative xh[src] gather-accumulate.
__global__ void __launch_bounds__(256)
k_agg(const float* __restrict__ eattr, const float* __restrict__ atten,
      const float* __restrict__ bias, int ce_off,
      float* __restrict__ wout, float* __restrict__ outp) {
    __shared__ float s_c[8][128];   // per-warp: 32 edges x 4 head-coefs
    __shared__ int   s_s[8][32];    // per-warp: 32 src ids
    int wrp = threadIdx.x >> 5;
    int n = blockIdx.x * 8 + wrp;
    int lane = threadIdx.x & 31;
    if (n >= NN) return;
    int r0 = g_rowstart[n], r1 = g_rowstart[n + 1];
    int deg = r1 - r0;
    int nchunk = (deg + 31) >> 5;
    float4 ad = *(const float4*)&g_adst[n * 4];
    float ce0 = g_ce[ce_off + 0], ce1 = g_ce[ce_off + 1];
    float ce2 = g_ce[ce_off + 2], ce3 = g_ce[ce_off + 3];

    // ---- phase 1: inline logits + online (max, expsum) ----
    float4 ra[3];
    int    rs[3], ro[3];
    float  rat[3];
    float m0 = NEGINF, m1 = NEGINF, m2 = NEGINF, m3 = NEGINF;
    float s0 = 0.f, s1 = 0.f, s2 = 0.f, s3 = 0.f;

#pragma unroll
    for (int c = 0; c < 3; c++) {
        ra[c] = make_float4(NEGINF, NEGINF, NEGINF, NEGINF);
        rs[c] = 0; ro[c] = 0; rat[c] = 0.f;
        if (c < nchunk) {
            int j = r0 + c * 32 + lane;
            bool valid = j < r1;
            if (valid) {
                int s = g_esrc_s[j];
                int orig = g_eid_s[j];
                float4 as4 = *(const float4*)&g_asrc[s * 4];
                float ea = __ldg(&eattr[orig]);
                float4 a;
                a.x = lrelu(as4.x + ea * ce0 + ad.x);
                a.y = lrelu(as4.y + ea * ce1 + ad.y);
                a.z = lrelu(as4.z + ea * ce2 + ad.z);
                a.w = lrelu(as4.w + ea * ce3 + ad.w);
                ra[c] = a; rs[c] = s; ro[c] = orig;
                rat[c] = __ldg(&atten[orig]);
                float t;
                t = fmaxf(m0, a.x); s0 = s0 * __expf(m0 - t) + __expf(a.x - t); m0 = t;
                t = fmaxf(m1, a.y); s1 = s1 * __expf(m1 - t) + __expf(a.y - t); m1 = t;
                t = fmaxf(m2, a.z); s2 = s2 * __expf(m2 - t) + __expf(a.z - t); m2 = t;
                t = fmaxf(m3, a.w); s3 = s3 * __expf(m3 - t) + __expf(a.w - t); m3 = t;
            }
        }
    }
    for (int c = 3; c < nchunk; c++) {          // rare spill path (deg > 96)
        int j = r0 + c * 32 + lane;
        if (j < r1) {
            int s = g_esrc_s[j];
            int orig = g_eid_s[j];
            float4 as4 = *(const float4*)&g_asrc[s * 4];
            float ea = __ldg(&eattr[orig]);
            float4 a;
            a.x = lrelu(as4.x + ea * ce0 + ad.x);
            a.y = lrelu(as4.y + ea * ce1 + ad.y);
            a.z = lrelu(as4.z + ea * ce2 + ad.z);
            a.w = lrelu(as4.w + ea * ce3 + ad.w);
            *(float4*)&g_alpha_s[(size_t)j * 4] = a;
            float t;
            t = fmaxf(m0, a.x); s0 = s0 * __expf(m0 - t) + __expf(a.x - t); m0 = t;
            t = fmaxf(m1, a.y); s1 = s1 * __expf(m1 - t) + __expf(a.y - t); m1 = t;
            t = fmaxf(m2, a.z); s2 = s2 * __expf(m2 - t) + __expf(a.z - t); m2 = t;
            t = fmaxf(m3, a.w); s3 = s3 * __expf(m3 - t) + __expf(a.w - t); m3 = t;
        }
    }
#pragma unroll
    for (int o = 16; o; o >>= 1) {
        float om, os, nm;
        om = __shfl_xor_sync(FULLM, m0, o); os = __shfl_xor_sync(FULLM, s0, o);
        nm = fmaxf(m0, om); s0 = s0 * __expf(m0 - nm) + os * __expf(om - nm); m0 = nm;
        om = __shfl_xor_sync(FULLM, m1, o); os = __shfl_xor_sync(FULLM, s1, o);
        nm = fmaxf(m1, om); s1 = s1 * __expf(m1 - nm) + os * __expf(om - nm); m1 = nm;
        om = __shfl_xor_sync(FULLM, m2, o); os = __shfl_xor_sync(FULLM, s2, o);
        nm = fmaxf(m2, om); s2 = s2 * __expf(m2 - nm) + os * __expf(om - nm); m2 = nm;
        om = __shfl_xor_sync(FULLM, m3, o); os = __shfl_xor_sync(FULLM, s3, o);
        nm = fmaxf(m3, om); s3 = s3 * __expf(m3 - nm) + os * __expf(om - nm); m3 = nm;
    }
    float i0 = 1.f / (s0 + 1e-16f), i1 = 1.f / (s1 + 1e-16f);
    float i2 = 1.f / (s2 + 1e-16f), i3 = 1.f / (s3 + 1e-16f);

    // ---- phase 2: wout scatter + gather-accumulate ----
    float acc0 = 0.f, acc1 = 0.f, acc2 = 0.f, acc3 = 0.f;
    float acc4 = 0.f, acc5 = 0.f, acc6 = 0.f, acc7 = 0.f;
    int h = lane >> 3;
    int c0 = lane * 8;

    for (int c = 0; c < nchunk; c++) {
        int base = r0 + c * 32;
        int j = base + lane;
        bool valid = j < r1;
        int cnt = min(32, r1 - base);
        float4 a; int s; float at; int orig;
        if (c < 3) {
            a = ra[c]; s = rs[c]; at = rat[c]; orig = ro[c];
        } else {
            s = valid ? g_esrc_s[j] : 0;
            orig = valid ? g_eid_s[j] : 0;
            a = valid ? *(const float4*)&g_alpha_s[(size_t)j * 4]
                      : make_float4(NEGINF, NEGINF, NEGINF, NEGINF);
            at = valid ? __ldg(&atten[orig]) : 0.f;
        }
        float w0 = __expf(a.x - m0) * i0;
        float w1 = __expf(a.y - m1) * i1;
        float w2 = __expf(a.z - m2) * i2;
        float w3 = __expf(a.w - m3) * i3;
        if (valid)
            *(float4*)&wout[(size_t)orig * 4] = make_float4(w0, w1, w2, w3);
        __syncwarp();
        *(float4*)&s_c[wrp][lane * 4] = make_float4(w0 * at, w1 * at, w2 * at, w3 * at);
        s_s[wrp][lane] = s;
        __syncwarp();
        for (int k = 0; k < cnt; k++) {
            float coef = s_c[wrp][k * 4 + h];
            int ss = s_s[wrp][k];
            const float4* xs = (const float4*)&g_xh[(size_t)ss * HC + c0];
            float4 v0 = xs[0];
            float4 v1 = xs[1];
            acc0 = fmaf(v0.x, coef, acc0); acc1 = fmaf(v0.y, coef, acc1);
            acc2 = fmaf(v0.z, coef, acc2); acc3 = fmaf(v0.w, coef, acc3);
            acc4 = fmaf(v1.x, coef, acc4); acc5 = fmaf(v1.y, coef, acc5);
            acc6 = fmaf(v1.z, coef, acc6); acc7 = fmaf(v1.w, coef, acc7);
        }
        __syncwarp();
    }

    float4 b0 = *(const float4*)&bias[c0];
    float4 b1 = *(const float4*)&bias[c0 + 4];
    float* op = outp ? &outp[(size_t)n * HC + c0] : &g_agg[(size_t)n * HC + c0];
    *(float4*)op = make_float4(acc0 + b0.x, acc1 + b0.y, acc2 + b0.z, acc3 + b0.w);
    *(float4*)(op + 4) = make_float4(acc4 + b1.x, acc5 + b1.y, acc6 + b1.z, acc7 + b1.w);
}

// ---------------- launch ---------------------------------------------------
extern "C" void kernel_launch(void* const* d_in, const int* in_sizes, int n_in,
                              void* d_out, int out_size) {
    const float* x       = (const float*)d_in[0];
    const int*   ei      = (const int*)d_in[1];
    const int*   src     = ei;
    const int*   dst     = ei + NE;
    const float* eattr   = (const float*)d_in[3];
    const float* eatten  = (const float*)d_in[4];
    const float* W1      = (const float*)d_in[5];
    const float* a_src1  = (const float*)d_in[6];
    const float* a_dst1  = (const float*)d_in[7];
    const float* W_e1    = (const float*)d_in[8];
    const float* a_e1    = (const float*)d_in[9];
    const float* b1      = (const float*)d_in[10];
    const float* W2      = (const float*)d_in[11];
    const float* a_src2  = (const float*)d_in[12];
    const float* a_dst2  = (const float*)d_in[13];
    const float* W_e2    = (const float*)d_in[14];
    const float* a_e2    = (const float*)d_in[15];
    const float* b2      = (const float*)d_in[16];

    float* out    = (float*)d_out;
    float* h_out  = out;                        // [NN, 256]
    float* w1_out = out + (size_t)NN * HC;      // [NE, 4]
    float* w2_out = w1_out + (size_t)NE * NH;   // [NE, 4]

    const int EB = (NE + 255) / 256;            // 2500
    const int NB = (NN + 255) / 256;            // 79
    const int AB = NN / 8;                      // 2500
    dim3 gemm_grid((NN + 127) / 128, NH);

    cudaFuncSetAttribute(k_scan, cudaFuncAttributeMaxDynamicSharedMemorySize, NN * 4);

    k_ce<<<1, 256>>>(W_e1, a_e1, W_e2, a_e2);

    // ---- CSR build (shared by both layers) ----
    k_zero_deg<<<NB, 256>>>();
    k_hist<<<EB, 256>>>(dst);
    k_scan<<<1, 1024, NN * 4>>>();
    k_scatter<<<EB, 256>>>(src, dst);

    // ---- layer 1 ----
    k_gemm<<<gemm_grid, 128>>>(x, W1, a_src1, a_dst1, 128);
    k_agg<<<AB, 256>>>(eattr, eatten, b1, 0, w1_out, nullptr);   // -> g_agg

    // ---- layer 2 ----
    k_gemm<<<gemm_grid, 128>>>(nullptr /*g_agg*/, W2, a_src2, a_dst2, 256);
    k_agg<<<AB, 256>>>(eattr, eatten, b2, 4, w2_out, h_out);
}

// round 8
// speedup vs baseline: 2.4503x; 1.2514x over previous
#include <cuda_runtime.h>
#include <cuda_fp16.h>
#include <cstdint>

#define NN 20000
#define NE 640000
#define HC 256      // H * C = 4 * 64
#define NH 4
#define FULLM 0xffffffffu
#define NEGINF -3.4e38f

// ---------------- scratch (static device globals; no allocation) ----------
__device__ __align__(16) __half g_xh[NN * HC];  // per-layer features (fp16 for gather BW)
__device__ float g_agg[NN * HC];       // h between layers (fp32)
__device__ float g_asrc[NN * NH];
__device__ float g_adst[NN * NH];
__device__ float g_alpha_s[NE * NH];   // spill buffer for deg > 96 nodes only
__device__ float g_ce[2 * NH];         // per-head edge-attr coefficient, both layers
// CSR
__device__ int g_deg[NN];
__device__ __align__(16) int g_rowstart[NN + 4];
__device__ int g_cursor[NN];
__device__ int g_esrc_s[NE];
__device__ int g_eid_s[NE];
__device__ __align__(8) float2 g_ea_s[NE];      // {eattr, atten} in CSR order

// ---------------- tiny setup kernels --------------------------------------
__global__ void k_ce(const float* __restrict__ We1, const float* __restrict__ ae1,
                     const float* __restrict__ We2, const float* __restrict__ ae2) {
    __shared__ float s1[256], s2[256];
    int t = threadIdx.x;
    s1[t] = We1[t] * ae1[t];
    s2[t] = We2[t] * ae2[t];
    __syncthreads();
    if (t < 8) {
        const float* s = (t >= 4) ? s2 : s1;
        int h = t & 3;
        float sum = 0.f;
#pragma unroll
        for (int c = 0; c < 64; c++) sum += s[h * 64 + c];
        g_ce[t] = sum;
    }
}

// ---------------- CSR build ------------------------------------------------
__global__ void k_zero_deg() {
    int i = blockIdx.x * blockDim.x + threadIdx.x;
    if (i < NN) g_deg[i] = 0;
}

__global__ void k_hist(const int* __restrict__ dst) {
    int e = blockIdx.x * blockDim.x + threadIdx.x;
    if (e < NE) atomicAdd(&g_deg[dst[e]], 1);
}

__global__ void k_scan() {
    extern __shared__ int sdeg[];       // NN ints
    __shared__ int wsum[32];
    int t = threadIdx.x;

    for (int i = t; i < NN / 4; i += 1024)
        ((int4*)sdeg)[i] = ((const int4*)g_deg)[i];
    __syncthreads();

    int loc[20];
    int tot = 0;
    if (t < 1000) {
        int base = t * 20;
#pragma unroll
        for (int i = 0; i < 20; i++) { loc[i] = tot; tot += sdeg[base + i]; }
    }
    int lane = t & 31, w = t >> 5;
    int v = tot;
#pragma unroll
    for (int o = 1; o < 32; o <<= 1) {
        int u = __shfl_up_sync(FULLM, v, o);
        if (lane >= o) v += u;
    }
    if (lane == 31) wsum[w] = v;
    __syncthreads();
    if (w == 0) {
        int s = wsum[lane];
#pragma unroll
        for (int o = 1; o < 32; o <<= 1) {
            int u = __shfl_up_sync(FULLM, s, o);
            if (lane >= o) s += u;
        }
        wsum[lane] = s;
    }
    __syncthreads();
    int excl = v - tot + (w ? wsum[w - 1] : 0);
    __syncthreads();
    if (t < 1000) {
        int base = t * 20;
#pragma unroll
        for (int i = 0; i < 20; i++) sdeg[base + i] = excl + loc[i];
    }
    __syncthreads();
    for (int i = t; i < NN / 4; i += 1024) {
        int4 r = ((const int4*)sdeg)[i];
        ((int4*)g_rowstart)[i] = r;
        ((int4*)g_cursor)[i] = r;
    }
    if (t == 0) g_rowstart[NN] = NE;
}

__global__ void k_scatter(const int* __restrict__ src, const int* __restrict__ dst,
                          const float* __restrict__ eattr, const float* __restrict__ atten) {
    int e = blockIdx.x * blockDim.x + threadIdx.x;
    if (e >= NE) return;
    int d = dst[e];
    int pos = atomicAdd(&g_cursor[d], 1);
    g_esrc_s[pos] = src[e];
    g_eid_s[pos] = e;
    g_ea_s[pos] = make_float2(eattr[e], atten[e]);
}

// ---------------- GEMM: xh = X @ W (fp16 out), fused alpha_src/alpha_dst ---
__global__ void __launch_bounds__(128)
k_gemm(const float* __restrict__ X, const float* __restrict__ W,
       const float* __restrict__ a_src, const float* __restrict__ a_dst, int K) {
    __shared__ __align__(16) float As[16][132];
    __shared__ __align__(16) float Bs[16][68];
    const float* Xp = X ? X : g_agg;

    int tid = threadIdx.x;
    int tx = tid & 7, ty = tid >> 3;
    int r0 = blockIdx.x * 128;
    int head = blockIdx.y;
    int c0 = head * 64;

    float acc[8][8] = {};

    for (int kk = 0; kk < K; kk += 16) {
#pragma unroll
        for (int l = 0; l < 4; l++) {
            int i = tid + 128 * l;
            int row = i >> 2;
            int kq = i & 3;
            float4 v = make_float4(0.f, 0.f, 0.f, 0.f);
            int gr = r0 + row;
            if (gr < NN) v = *(const float4*)&Xp[(size_t)gr * K + kk + kq * 4];
            As[kq * 4 + 0][row] = v.x;
            As[kq * 4 + 1][row] = v.y;
            As[kq * 4 + 2][row] = v.z;
            As[kq * 4 + 3][row] = v.w;
        }
#pragma unroll
        for (int l = 0; l < 2; l++) {
            int i = tid + 128 * l;
            int kr = i >> 4;
            int cq = i & 15;
            float4 v = *(const float4*)&W[(size_t)(kk + kr) * HC + c0 + cq * 4];
            *(float4*)&Bs[kr][cq * 4] = v;
        }
        __syncthreads();
#pragma unroll
        for (int k = 0; k < 16; k++) {
            float4 a0 = *(float4*)&As[k][ty * 4];
            float4 a1 = *(float4*)&As[k][64 + ty * 4];
            float4 b0 = *(float4*)&Bs[k][tx * 4];
            float4 b1 = *(float4*)&Bs[k][32 + tx * 4];
            float ar[8] = {a0.x, a0.y, a0.z, a0.w, a1.x, a1.y, a1.z, a1.w};
            float br[8] = {b0.x, b0.y, b0.z, b0.w, b1.x, b1.y, b1.z, b1.w};
#pragma unroll
            for (int i = 0; i < 8; i++)
#pragma unroll
                for (int j = 0; j < 8; j++)
                    acc[i][j] = fmaf(ar[i], br[j], acc[i][j]);
        }
        __syncthreads();
    }

    float4 as0 = *(const float4*)&a_src[head * 64 + tx * 4];
    float4 as1 = *(const float4*)&a_src[head * 64 + 32 + tx * 4];
    float4 ad0 = *(const float4*)&a_dst[head * 64 + tx * 4];
    float4 ad1 = *(const float4*)&a_dst[head * 64 + 32 + tx * 4];
    float asv[8] = {as0.x, as0.y, as0.z, as0.w, as1.x, as1.y, as1.z, as1.w};
    float adv[8] = {ad0.x, ad0.y, ad0.z, ad0.w, ad1.x, ad1.y, ad1.z, ad1.w};

#pragma unroll
    for (int i = 0; i < 8; i++) {
        int gr = r0 + ((i < 4) ? (ty * 4 + i) : (64 + ty * 4 + i - 4));
        float ps = 0.f, pd = 0.f;
#pragma unroll
        for (int j = 0; j < 8; j++) {
            ps = fmaf(acc[i][j], asv[j], ps);
            pd = fmaf(acc[i][j], adv[j], pd);
        }
#pragma unroll
        for (int o = 4; o; o >>= 1) {
            ps += __shfl_down_sync(FULLM, ps, o, 8);
            pd += __shfl_down_sync(FULLM, pd, o, 8);
        }
        if (gr < NN) {
            __half2 h01 = __floats2half2_rn(acc[i][0], acc[i][1]);
            __half2 h23 = __floats2half2_rn(acc[i][2], acc[i][3]);
            __half2 h45 = __floats2half2_rn(acc[i][4], acc[i][5]);
            __half2 h67 = __floats2half2_rn(acc[i][6], acc[i][7]);
            __half2* xp = (__half2*)&g_xh[(size_t)gr * HC + c0];
            xp[tx * 2 + 0] = h01;
            xp[tx * 2 + 1] = h23;
            xp[16 + tx * 2 + 0] = h45;
            xp[16 + tx * 2 + 1] = h67;
            if (tx == 0) {
                g_asrc[gr * NH + head] = ps;
                g_adst[gr * NH + head] = pd;
            }
        }
    }
}

__device__ __forceinline__ float lrelu(float v) { return v >= 0.f ? v : 0.2f * v; }

struct __align__(16) h8 { __half2 a, b, c, d; };

// ---------------- fused logits + softmax + aggregation ---------------------
__global__ void __launch_bounds__(256)
k_agg(const float* __restrict__ bias, int ce_off,
      float* __restrict__ wout, float* __restrict__ outp) {
    __shared__ float s_c[8][128];   // per-warp: 32 edges x 4 head-coefs
    __shared__ int   s_s[8][32];    // per-warp: 32 src ids
    int wrp = threadIdx.x >> 5;
    int n = blockIdx.x * 8 + wrp;
    int lane = threadIdx.x & 31;
    if (n >= NN) return;
    int r0 = g_rowstart[n], r1 = g_rowstart[n + 1];
    int deg = r1 - r0;
    int nchunk = (deg + 31) >> 5;
    float4 ad = *(const float4*)&g_adst[n * 4];
    float ce0 = g_ce[ce_off + 0], ce1 = g_ce[ce_off + 1];
    float ce2 = g_ce[ce_off + 2], ce3 = g_ce[ce_off + 3];

    // ---- phase 1: inline logits + online (max, expsum) ----
    float4 ra[3];
    int    rs[3], ro[3];
    float  rat[3];
    float m0 = NEGINF, m1 = NEGINF, m2 = NEGINF, m3 = NEGINF;
    float s0 = 0.f, s1 = 0.f, s2 = 0.f, s3 = 0.f;

#pragma unroll
    for (int c = 0; c < 3; c++) {
        ra[c] = make_float4(NEGINF, NEGINF, NEGINF, NEGINF);
        rs[c] = 0; ro[c] = 0; rat[c] = 0.f;
        if (c < nchunk) {
            int j = r0 + c * 32 + lane;
            if (j < r1) {
                int s = g_esrc_s[j];
                int orig = g_eid_s[j];
                float2 ea2 = g_ea_s[j];
                float4 as4 = *(const float4*)&g_asrc[s * 4];
                float4 a;
                a.x = lrelu(as4.x + ea2.x * ce0 + ad.x);
                a.y = lrelu(as4.y + ea2.x * ce1 + ad.y);
                a.z = lrelu(as4.z + ea2.x * ce2 + ad.z);
                a.w = lrelu(as4.w + ea2.x * ce3 + ad.w);
                ra[c] = a; rs[c] = s; ro[c] = orig; rat[c] = ea2.y;
                float t;
                t = fmaxf(m0, a.x); s0 = s0 * __expf(m0 - t) + __expf(a.x - t); m0 = t;
                t = fmaxf(m1, a.y); s1 = s1 * __expf(m1 - t) + __expf(a.y - t); m1 = t;
                t = fmaxf(m2, a.z); s2 = s2 * __expf(m2 - t) + __expf(a.z - t); m2 = t;
                t = fmaxf(m3, a.w); s3 = s3 * __expf(m3 - t) + __expf(a.w - t); m3 = t;
            }
        }
    }
    for (int c = 3; c < nchunk; c++) {          // rare spill path (deg > 96)
        int j = r0 + c * 32 + lane;
        if (j < r1) {
            int s = g_esrc_s[j];
            float2 ea2 = g_ea_s[j];
            float4 as4 = *(const float4*)&g_asrc[s * 4];
            float4 a;
            a.x = lrelu(as4.x + ea2.x * ce0 + ad.x);
            a.y = lrelu(as4.y + ea2.x * ce1 + ad.y);
            a.z = lrelu(as4.z + ea2.x * ce2 + ad.z);
            a.w = lrelu(as4.w + ea2.x * ce3 + ad.w);
            *(float4*)&g_alpha_s[(size_t)j * 4] = a;
            float t;
            t = fmaxf(m0, a.x); s0 = s0 * __expf(m0 - t) + __expf(a.x - t); m0 = t;
            t = fmaxf(m1, a.y); s1 = s1 * __expf(m1 - t) + __expf(a.y - t); m1 = t;
            t = fmaxf(m2, a.z); s2 = s2 * __expf(m2 - t) + __expf(a.z - t); m2 = t;
            t = fmaxf(m3, a.w); s3 = s3 * __expf(m3 - t) + __expf(a.w - t); m3 = t;
        }
    }
#pragma unroll
    for (int o = 16; o; o >>= 1) {
        float om, os, nm;
        om = __shfl_xor_sync(FULLM, m0, o); os = __shfl_xor_sync(FULLM, s0, o);
        nm = fmaxf(m0, om); s0 = s0 * __expf(m0 - nm) + os * __expf(om - nm); m0 = nm;
        om = __shfl_xor_sync(FULLM, m1, o); os = __shfl_xor_sync(FULLM, s1, o);
        nm = fmaxf(m1, om); s1 = s1 * __expf(m1 - nm) + os * __expf(om - nm); m1 = nm;
        om = __shfl_xor_sync(FULLM, m2, o); os = __shfl_xor_sync(FULLM, s2, o);
        nm = fmaxf(m2, om); s2 = s2 * __expf(m2 - nm) + os * __expf(om - nm); m2 = nm;
        om = __shfl_xor_sync(FULLM, m3, o); os = __shfl_xor_sync(FULLM, s3, o);
        nm = fmaxf(m3, om); s3 = s3 * __expf(m3 - nm) + os * __expf(om - nm); m3 = nm;
    }
    float i0 = 1.f / (s0 + 1e-16f), i1 = 1.f / (s1 + 1e-16f);
    float i2 = 1.f / (s2 + 1e-16f), i3 = 1.f / (s3 + 1e-16f);

    // ---- phase 2: wout scatter + fp16 gather-accumulate ----
    float acc0 = 0.f, acc1 = 0.f, acc2 = 0.f, acc3 = 0.f;
    float acc4 = 0.f, acc5 = 0.f, acc6 = 0.f, acc7 = 0.f;
    int h = lane >> 3;
    int c0 = lane * 8;

    for (int c = 0; c < nchunk; c++) {
        int base = r0 + c * 32;
        int j = base + lane;
        bool valid = j < r1;
        int cnt = min(32, r1 - base);
        float4 a; int s; float at; int orig;
        if (c < 3) {
            a = ra[c]; s = rs[c]; at = rat[c]; orig = ro[c];
        } else {
            s = valid ? g_esrc_s[j] : 0;
            orig = valid ? g_eid_s[j] : 0;
            float2 ea2 = valid ? g_ea_s[j] : make_float2(0.f, 0.f);
            a = valid ? *(const float4*)&g_alpha_s[(size_t)j * 4]
                      : make_float4(NEGINF, NEGINF, NEGINF, NEGINF);
            at = ea2.y;
        }
        float w0 = __expf(a.x - m0) * i0;
        float w1 = __expf(a.y - m1) * i1;
        float w2 = __expf(a.z - m2) * i2;
        float w3 = __expf(a.w - m3) * i3;
        if (valid)
            *(float4*)&wout[(size_t)orig * 4] = make_float4(w0, w1, w2, w3);
        __syncwarp();
        *(float4*)&s_c[wrp][lane * 4] = make_float4(w0 * at, w1 * at, w2 * at, w3 * at);
        s_s[wrp][lane] = s;
        __syncwarp();
        for (int k = 0; k < cnt; k++) {
            float coef = s_c[wrp][k * 4 + h];
            int ss = s_s[wrp][k];
            h8 v = *(const h8*)&g_xh[(size_t)ss * HC + c0];
            float2 f0 = __half22float2(v.a);
            float2 f1 = __half22float2(v.b);
            float2 f2 = __half22float2(v.c);
            float2 f3 = __half22float2(v.d);
            acc0 = fmaf(f0.x, coef, acc0); acc1 = fmaf(f0.y, coef, acc1);
            acc2 = fmaf(f1.x, coef, acc2); acc3 = fmaf(f1.y, coef, acc3);
            acc4 = fmaf(f2.x, coef, acc4); acc5 = fmaf(f2.y, coef, acc5);
            acc6 = fmaf(f3.x, coef, acc6); acc7 = fmaf(f3.y, coef, acc7);
        }
        __syncwarp();
    }

    float4 b0 = *(const float4*)&bias[c0];
    float4 b1 = *(const float4*)&bias[c0 + 4];
    float* op = outp ? &outp[(size_t)n * HC + c0] : &g_agg[(size_t)n * HC + c0];
    *(float4*)op = make_float4(acc0 + b0.x, acc1 + b0.y, acc2 + b0.z, acc3 + b0.w);
    *(float4*)(op + 4) = make_float4(acc4 + b1.x, acc5 + b1.y, acc6 + b1.z, acc7 + b1.w);
}

// ---------------- launch ---------------------------------------------------
extern "C" void kernel_launch(void* const* d_in, const int* in_sizes, int n_in,
                              void* d_out, int out_size) {
    const float* x       = (const float*)d_in[0];
    const int*   ei      = (const int*)d_in[1];
    const int*   src     = ei;
    const int*   dst     = ei + NE;
    const float* eattr   = (const float*)d_in[3];
    const float* eatten  = (const float*)d_in[4];
    const float* W1      = (const float*)d_in[5];
    const float* a_src1  = (const float*)d_in[6];
    const float* a_dst1  = (const float*)d_in[7];
    const float* W_e1    = (const float*)d_in[8];
    const float* a_e1    = (const float*)d_in[9];
    const float* b1      = (const float*)d_in[10];
    const float* W2      = (const float*)d_in[11];
    const float* a_src2  = (const float*)d_in[12];
    const float* a_dst2  = (const float*)d_in[13];
    const float* W_e2    = (const float*)d_in[14];
    const float* a_e2    = (const float*)d_in[15];
    const float* b2      = (const float*)d_in[16];

    float* out    = (float*)d_out;
    float* h_out  = out;                        // [NN, 256]
    float* w1_out = out + (size_t)NN * HC;      // [NE, 4]
    float* w2_out = w1_out + (size_t)NE * NH;   // [NE, 4]

    const int EB = (NE + 255) / 256;            // 2500
    const int NB = (NN + 255) / 256;            // 79
    const int AB = NN / 8;                      // 2500
    dim3 gemm_grid((NN + 127) / 128, NH);

    cudaFuncSetAttribute(k_scan, cudaFuncAttributeMaxDynamicSharedMemorySize, NN * 4);

    k_ce<<<1, 256>>>(W_e1, a_e1, W_e2, a_e2);

    // ---- CSR build (shared by both layers) ----
    k_zero_deg<<<NB, 256>>>();
    k_hist<<<EB, 256>>>(dst);
    k_scan<<<1, 1024, NN * 4>>>();
    k_scatter<<<EB, 256>>>(src, dst, eattr, eatten);

    // ---- layer 1 ----
    k_gemm<<<gemm_grid, 128>>>(x, W1, a_src1, a_dst1, 128);
    k_agg<<<AB, 256>>>(b1, 0, w1_out, nullptr);   // -> g_agg

    // ---- layer 2 ----
    k_gemm<<<gemm_grid, 128>>>(nullptr /*g_agg*/, W2, a_src2, a_dst2, 256);
    k_agg<<<AB, 256>>>(b2, 4, w2_out, h_out);
}